// round 6
// baseline (speedup 1.0000x reference)
#include <cuda_runtime.h>
#include <cuda_bf16.h>
#include <math.h>

typedef unsigned int uint32;

// ============================================================================
// HeadGroupedFusionGate, mma.sync bf16 3-term split (x*w ~ xh*wh + xl*wh + xh*wl).
// R6: A fragments built directly in registers from gmem (no A smem / ldsm),
//     warp tile 32x32, double-buffered pipelined B, 512-thr k_tail.
// ============================================================================

__device__ __nv_bfloat16 g_Wh[21 * 64 * 136];
__device__ __nv_bfloat16 g_Wl[21 * 64 * 136];
__device__ float g_hidcA[4096 * 128];
__device__ float g_hidcB[4096 * 128];

// ---- PTX helpers ----
__device__ __forceinline__ uint32 smem_u32(const void* p) {
    uint32 a;
    asm("{ .reg .u64 t; cvta.to.shared.u64 t, %1; cvt.u32.u64 %0, t; }" : "=r"(a) : "l"(p));
    return a;
}
__device__ __forceinline__ void cpa16(uint32 s, const void* g) {
    asm volatile("cp.async.cg.shared.global [%0], [%1], 16;" :: "r"(s), "l"(g));
}
#define CPA_COMMIT() asm volatile("cp.async.commit_group;")
#define CPA_WAIT0()  asm volatile("cp.async.wait_group 0;")

__device__ __forceinline__ void ldsm4(uint32* r, uint32 a) {
    asm volatile("ldmatrix.sync.aligned.m8n8.x4.shared.b16 {%0,%1,%2,%3}, [%4];"
        : "=r"(r[0]), "=r"(r[1]), "=r"(r[2]), "=r"(r[3]) : "r"(a));
}
__device__ __forceinline__ void ldsm4t(uint32* r, uint32 a) {
    asm volatile("ldmatrix.sync.aligned.m8n8.x4.trans.shared.b16 {%0,%1,%2,%3}, [%4];"
        : "=r"(r[0]), "=r"(r[1]), "=r"(r[2]), "=r"(r[3]) : "r"(a));
}
__device__ __forceinline__ void mma16816(float* d, const uint32* a, uint32 b0, uint32 b1) {
    asm volatile("mma.sync.aligned.m16n8k16.row.col.f32.bf16.bf16.f32 "
        "{%0,%1,%2,%3}, {%4,%5,%6,%7}, {%8,%9}, {%0,%1,%2,%3};"
        : "+f"(d[0]), "+f"(d[1]), "+f"(d[2]), "+f"(d[3])
        : "r"(a[0]), "r"(a[1]), "r"(a[2]), "r"(a[3]), "r"(b0), "r"(b1));
}
__device__ __forceinline__ void cvtpair(float v0, float v1, uint32& h, uint32& l) {
    __nv_bfloat162 hp = __floats2bfloat162_rn(v0, v1);
    h = *(uint32*)&hp;
    float r0 = v0 - __bfloat162float(hp.x);
    float r1 = v1 - __bfloat162float(hp.y);
    __nv_bfloat162 lp = __floats2bfloat162_rn(r0, r1);
    l = *(uint32*)&lp;
}

// raw[2*s4+c]: s4 = row-slot (rows rb+q4+8*s4), c=0: cols kc+2q..+1, c=1: +8
__device__ __forceinline__ void make_frags(const float2* raw,
                                           uint32 (&ah)[2][4], uint32 (&al)[2][4]) {
#pragma unroll
    for (int m = 0; m < 2; ++m) {
        cvtpair(raw[4*m+0].x, raw[4*m+0].y, ah[m][0], al[m][0]);
        cvtpair(raw[4*m+2].x, raw[4*m+2].y, ah[m][1], al[m][1]);
        cvtpair(raw[4*m+1].x, raw[4*m+1].y, ah[m][2], al[m][2]);
        cvtpair(raw[4*m+3].x, raw[4*m+3].y, ah[m][3], al[m][3]);
    }
}

// one k16 step: 2 Mtiles x 4 n8 tiles x 3 split terms = 24 mma, B via 4 ldsm4t
__device__ __forceinline__ void mma_nk(float (&acc)[2][4][4],
                                       uint32 (&ah)[2][4], uint32 (&al)[2][4],
                                       uint32 bhA, uint32 blA) {
    uint32 bh0[4], bh1[4], bl0[4], bl1[4];
    ldsm4t(bh0, bhA); ldsm4t(bh1, bhA + 32);
    ldsm4t(bl0, blA); ldsm4t(bl1, blA + 32);
#pragma unroll
    for (int m = 0; m < 2; ++m) {
        mma16816(acc[m][0], ah[m], bh0[0], bh0[1]);
        mma16816(acc[m][1], ah[m], bh0[2], bh0[3]);
        mma16816(acc[m][2], ah[m], bh1[0], bh1[1]);
        mma16816(acc[m][3], ah[m], bh1[2], bh1[3]);
        mma16816(acc[m][0], al[m], bh0[0], bh0[1]);
        mma16816(acc[m][1], al[m], bh0[2], bh0[3]);
        mma16816(acc[m][2], al[m], bh1[0], bh1[1]);
        mma16816(acc[m][3], al[m], bh1[2], bh1[3]);
        mma16816(acc[m][0], ah[m], bl0[0], bl0[1]);
        mma16816(acc[m][1], ah[m], bl0[2], bl0[3]);
        mma16816(acc[m][2], ah[m], bl1[0], bl1[1]);
        mma16816(acc[m][3], ah[m], bl1[2], bl1[3]);
    }
}

// ============================================================================
// k_prep (unchanged from R5)
// ============================================================================
__global__ void __launch_bounds__(128) k_prep(const float* __restrict__ W1) {
    int b = blockIdx.x, tid = threadIdx.x;
    if (b < 160) {
        int rr0 = b * 8;
#pragma unroll
        for (int j = 0; j < 8; ++j) {
            int rr = rr0 + j;
            int c = rr >> 6, k = rr & 63;
            int row = (c < 16) ? c * 64 + k : 1792 + (c - 16) * 64 + k;
            float v = W1[(size_t)row * 128 + tid];
            __nv_bfloat16 h = __float2bfloat16_rn(v);
            g_Wh[rr * 136 + tid] = h;
            g_Wl[rr * 136 + tid] = __float2bfloat16_rn(v - __bfloat162float(h));
        }
    } else if (b < 172) {
        int k = b - 160;
        int row0 = 1024 + (k / 3) * 192 + (k % 3) * 64;
        float s = 0.f;
#pragma unroll 8
        for (int d = 0; d < 64; ++d) s += W1[(size_t)(row0 + d) * 128 + tid];
        __nv_bfloat16 h = __float2bfloat16_rn(s);
        g_Wh[(1280 + k) * 136 + tid] = h;
        g_Wl[(1280 + k) * 136 + tid] = __float2bfloat16_rn(s - __bfloat162float(h));
    } else {
        __nv_bfloat16 z = __float2bfloat16_rn(0.f);
#pragma unroll
        for (int k = 12; k < 16; ++k) {
            g_Wh[(1280 + k) * 136 + tid] = z;
            g_Wl[(1280 + k) * 136 + tid] = z;
        }
    }
}

// ============================================================================
// k_hid: grid 128 (bid>>1 = 64-token group, bid&1 = K half), 256 thr = 8 warps.
// warp = 32 rows x 32 N-cols (rowg = w>>2 in {0,1}, colg = w&3).
// smem: B double buffer 2 x (Bh 17408 + Bl 17408) = 69632.
// ============================================================================
#define H_SMEM 69632

__global__ void __launch_bounds__(256, 2) k_hid(const float* __restrict__ hidden) {
    extern __shared__ char sm[];
    uint32 sb = smem_u32(sm);
    int tid = threadIdx.x, lane = tid & 31, w = tid >> 5;
    int rowg = w >> 2, colg = w & 3;
    int rb = rowg * 32, q4 = lane >> 2, q = lane & 3;
    int tg = blockIdx.x >> 1, khalf = blockIdx.x & 1;
    int tok0 = tg * 64;

    float acc[2][4][4];
#pragma unroll
    for (int m = 0; m < 2; ++m)
#pragma unroll
        for (int n = 0; n < 4; ++n)
#pragma unroll
            for (int i = 0; i < 4; ++i) acc[m][n][i] = 0.f;

    uint32 boff = ((lane & 7) + ((lane >> 3) & 1) * 8) * 272 + ((lane >> 4) & 1) * 16;

    { // B chunk 0
        int c = khalf * 8;
        const char* wh = (const char*)g_Wh + (size_t)c * 17408;
        const char* wl = (const char*)g_Wl + (size_t)c * 17408;
        for (int u = tid; u < 1088; u += 256) {
            cpa16(sb + u * 16, wh + (size_t)u * 16);
            cpa16(sb + 17408 + u * 16, wl + (size_t)u * 16);
        }
        CPA_COMMIT();
    }

    const float2* Ab = (const float2*)hidden + (size_t)tok0 * 512;

    for (int p = 0; p < 8; ++p) {
        CPA_WAIT0();
        __syncthreads();
        if (p < 7) {
            int c = khalf * 8 + p + 1;
            uint32 bbuf = sb + ((p + 1) & 1) * 34816;
            const char* wh = (const char*)g_Wh + (size_t)c * 17408;
            const char* wl = (const char*)g_Wl + (size_t)c * 17408;
            for (int u = tid; u < 1088; u += 256) {
                cpa16(bbuf + u * 16, wh + (size_t)u * 16);
                cpa16(bbuf + 17408 + u * 16, wl + (size_t)u * 16);
            }
            CPA_COMMIT();
        }
        int c = khalf * 8 + p;
        uint32 bhA = sb + (p & 1) * 34816 + boff + colg * 64;
        uint32 blA = bhA + 17408;
#pragma unroll
        for (int k = 0; k < 4; ++k) {
            float2 raw[8];
#pragma unroll
            for (int s4 = 0; s4 < 4; ++s4) {
                const float2* rp = Ab + (size_t)(rb + q4 + 8 * s4) * 512 + c * 32 + 8 * k + q;
                raw[2 * s4] = rp[0];
                raw[2 * s4 + 1] = rp[4];
            }
            uint32 ah[2][4], al[2][4];
            make_frags(raw, ah, al);
            mma_nk(acc, ah, al, bhA + k * 4352, blA + k * 4352);
        }
    }

    float* dst = khalf ? g_hidcB : g_hidcA;
    int cb = colg * 32;
#pragma unroll
    for (int m = 0; m < 2; ++m)
#pragma unroll
        for (int n = 0; n < 4; ++n) {
            int c0 = cb + n * 8 + 2 * q;
            int rA = rb + 16 * m + q4;
            *(float2*)&dst[(size_t)(tok0 + rA) * 128 + c0] = make_float2(acc[m][n][0], acc[m][n][1]);
            *(float2*)&dst[(size_t)(tok0 + rA + 8) * 128 + c0] = make_float2(acc[m][n][2], acc[m][n][3]);
        }
}

// ============================================================================
// k_tail: grid 512, 512 thr = 16 warps. CTA = 8 tokens x 16 heads = 128 rows.
// warp = 32 rows x 32 N-cols (rowg = w>>2, colg = w&3).
// smem (bytes): B double 0..69631 | ASH 69632 (128x48) | ASL 75776 |
//               HID 81920 (4KB) | W2S 86016 (2KB) | SHP 88064 (8KB) | MSC 96256
// ============================================================================
#define T_ASH 69632
#define T_ASL 75776
#define T_HID 81920
#define T_W2S 86016
#define T_SHP 88064
#define T_MSC 96256
#define T_SMEM 96768

__global__ void __launch_bounds__(512) k_tail(
    const float* __restrict__ br0, const float* __restrict__ br1,
    const float* __restrict__ br2, const float* __restrict__ br3,
    const float* __restrict__ b1, const float* __restrict__ W2,
    const float* __restrict__ b2, const float* __restrict__ epsf,
    const float* __restrict__ temp, float* __restrict__ out) {
    extern __shared__ char sm[];
    uint32 sb = smem_u32(sm);
    int tid = threadIdx.x, lane = tid & 31, w = tid >> 5;
    int rowg = w >> 2, colg = w & 3;
    int rb = rowg * 32, cb = colg * 32;
    int q4 = lane >> 2, q = lane & 3;
    int tok0 = blockIdx.x * 8;
    const float* brs[4] = {br0, br1, br2, br3};

    // prologue: epilogue data + stat-tile zero pad (cols 12..15)
    if (tid < 256) {
        int row = tid >> 5, c4 = tid & 31;
        float4 a = *(const float4*)&g_hidcA[(size_t)(tok0 + row) * 128 + c4 * 4];
        float4 b = *(const float4*)&g_hidcB[(size_t)(tok0 + row) * 128 + c4 * 4];
        float4 c = ((const float4*)b1)[c4];
        *(float4*)(sm + T_HID + tid * 16) =
            make_float4(a.x + b.x + c.x, a.y + b.y + c.y, a.z + b.z + c.z, a.w + b.w + c.w);
    }
    if (tid < 128) {
        *(float4*)(sm + T_W2S + tid * 16) = ((const float4*)W2)[tid];
        *(uint2*)(sm + T_ASH + tid * 48 + 24) = make_uint2(0u, 0u);
        *(uint2*)(sm + T_ASL + tid * 48 + 24) = make_uint2(0u, 0u);
    }
    {
        float* msc = (float*)(sm + T_MSC);
        if (tid < 4)  msc[tid] = b2[tid];
        if (tid < 16) msc[4 + tid] = temp[tid];
        if (tid < 64) msc[20 + tid] = epsf[tid];
    }

    float acc[2][4][4];
#pragma unroll
    for (int m = 0; m < 2; ++m)
#pragma unroll
        for (int n = 0; n < 4; ++n)
#pragma unroll
            for (int i = 0; i < 4; ++i) acc[m][n][i] = 0.f;

    uint32 boff = ((lane & 7) + ((lane >> 3) & 1) * 8) * 272 + ((lane >> 4) & 1) * 16;

    { // B chunk 0 (branch 0 weights)
        const char* wh = (const char*)g_Wh + (size_t)16 * 17408;
        const char* wl = (const char*)g_Wl + (size_t)16 * 17408;
        for (int u = tid; u < 1088; u += 512) {
            cpa16(sb + u * 16, wh + (size_t)u * 16);
            cpa16(sb + 17408 + u * 16, wl + (size_t)u * 16);
        }
        CPA_COMMIT();
    }

    for (int p = 0; p <= 4; ++p) {
        CPA_WAIT0();
        __syncthreads();
        if (p < 4) { // issue B for chunk p+1
            int cn = p + 1;
            uint32 bbuf = sb + ((p + 1) & 1) * 34816;
            int chunk = (cn < 4) ? 16 + cn : 20;
            int units = (cn < 4) ? 1088 : 272;
            const char* wh = (const char*)g_Wh + (size_t)chunk * 17408;
            const char* wl = (const char*)g_Wl + (size_t)chunk * 17408;
            for (int u = tid; u < units; u += 512) {
                cpa16(bbuf + u * 16, wh + (size_t)u * 16);
                cpa16(bbuf + 17408 + u * 16, wl + (size_t)u * 16);
            }
            CPA_COMMIT();
        }
        uint32 bhA = sb + (p & 1) * 34816 + boff + colg * 64;
        uint32 blA = bhA + 17408;

        if (p < 4) {
            const float2* Ab = (const float2*)brs[p] + (size_t)tok0 * 16 * 32;
            float st_s[4], st_q[4], st_m[4];
            if (colg == 0) {
#pragma unroll
                for (int s4 = 0; s4 < 4; ++s4) { st_s[s4] = 0.f; st_q[s4] = 0.f; st_m[s4] = -INFINITY; }
            }
#pragma unroll
            for (int k = 0; k < 4; ++k) {
                float2 raw[8];
#pragma unroll
                for (int s4 = 0; s4 < 4; ++s4) {
                    const float2* rp = Ab + (size_t)(rb + q4 + 8 * s4) * 32 + 8 * k + q;
                    raw[2 * s4] = rp[0];
                    raw[2 * s4 + 1] = rp[4];
                }
                if (colg == 0) {
#pragma unroll
                    for (int s4 = 0; s4 < 4; ++s4) {
                        float2 a = raw[2 * s4], b = raw[2 * s4 + 1];
                        st_s[s4] += a.x + a.y + b.x + b.y;
                        st_q[s4] = fmaf(a.x, a.x, fmaf(a.y, a.y, fmaf(b.x, b.x, fmaf(b.y, b.y, st_q[s4]))));
                        st_m[s4] = fmaxf(st_m[s4], fmaxf(fmaxf(a.x, a.y), fmaxf(b.x, b.y)));
                    }
                }
                uint32 ah[2][4], al[2][4];
                make_frags(raw, ah, al);
                mma_nk(acc, ah, al, bhA + k * 4352, blA + k * 4352);
            }
            if (colg == 0) {
#pragma unroll
                for (int s4 = 0; s4 < 4; ++s4) {
#pragma unroll
                    for (int d = 1; d <= 2; d <<= 1) {
                        st_s[s4] += __shfl_xor_sync(0xffffffffu, st_s[s4], d);
                        st_q[s4] += __shfl_xor_sync(0xffffffffu, st_q[s4], d);
                        st_m[s4] = fmaxf(st_m[s4], __shfl_xor_sync(0xffffffffu, st_m[s4], d));
                    }
                }
                if (q == 0) {
#pragma unroll
                    for (int s4 = 0; s4 < 4; ++s4) {
                        int row = rb + q4 + 8 * s4;
                        float v3[3];
                        v3[0] = st_s[s4] * 0.015625f;
                        v3[1] = sqrtf(fmaxf(st_q[s4] * 0.015625f, 1e-8f));
                        v3[2] = st_m[s4];
#pragma unroll
                        for (int j = 0; j < 3; ++j) {
                            __nv_bfloat16 h = __float2bfloat16_rn(v3[j]);
                            *(__nv_bfloat16*)(sm + T_ASH + row * 48 + (p * 3 + j) * 2) = h;
                            *(__nv_bfloat16*)(sm + T_ASL + row * 48 + (p * 3 + j) * 2) =
                                __float2bfloat16_rn(v3[j] - __bfloat162float(h));
                        }
                    }
                }
            }
        } else {
            // stats chunk (K=16): A from ASH/ASL via ldmatrix
            uint32 ah[2][4], al[2][4];
            uint32 aoff = (uint32)((rb + (lane & 15)) * 48 + (lane >> 4) * 16);
            ldsm4(ah[0], sb + T_ASH + aoff);
            ldsm4(ah[1], sb + T_ASH + aoff + 768);
            ldsm4(al[0], sb + T_ASL + aoff);
            ldsm4(al[1], sb + T_ASL + aoff + 768);
            mma_nk(acc, ah, al, bhA, blA);
        }
    }

    // ---- epilogue: gelu + W2 partial logits ----
    float lg[4][4];
#pragma unroll
    for (int s = 0; s < 4; ++s)
#pragma unroll
        for (int j = 0; j < 4; ++j) lg[s][j] = 0.f;

#pragma unroll
    for (int m = 0; m < 2; ++m) {
        int tokc = rowg * 2 + m;
#pragma unroll
        for (int n = 0; n < 4; ++n) {
            int c0 = cb + n * 8 + 2 * q;
            float2 hv = *(const float2*)(sm + T_HID + (tokc * 128 + c0) * 4);
            float4 wa = *(const float4*)(sm + T_W2S + c0 * 16);
            float4 wb = *(const float4*)(sm + T_W2S + (c0 + 1) * 16);
            float v0 = acc[m][n][0] + hv.x, v1 = acc[m][n][1] + hv.y;
            float v2 = acc[m][n][2] + hv.x, v3 = acc[m][n][3] + hv.y;
            float g0 = v0 * normcdff(v0), g1 = v1 * normcdff(v1);
            float g2 = v2 * normcdff(v2), g3 = v3 * normcdff(v3);
            lg[2 * m][0] = fmaf(g0, wa.x, fmaf(g1, wb.x, lg[2 * m][0]));
            lg[2 * m][1] = fmaf(g0, wa.y, fmaf(g1, wb.y, lg[2 * m][1]));
            lg[2 * m][2] = fmaf(g0, wa.z, fmaf(g1, wb.z, lg[2 * m][2]));
            lg[2 * m][3] = fmaf(g0, wa.w, fmaf(g1, wb.w, lg[2 * m][3]));
            lg[2 * m + 1][0] = fmaf(g2, wa.x, fmaf(g3, wb.x, lg[2 * m + 1][0]));
            lg[2 * m + 1][1] = fmaf(g2, wa.y, fmaf(g3, wb.y, lg[2 * m + 1][1]));
            lg[2 * m + 1][2] = fmaf(g2, wa.z, fmaf(g3, wb.z, lg[2 * m + 1][2]));
            lg[2 * m + 1][3] = fmaf(g2, wa.w, fmaf(g3, wb.w, lg[2 * m + 1][3]));
        }
    }
#pragma unroll
    for (int d = 1; d <= 2; d <<= 1)
#pragma unroll
        for (int s = 0; s < 4; ++s)
#pragma unroll
            for (int j = 0; j < 4; ++j)
                lg[s][j] += __shfl_xor_sync(0xffffffffu, lg[s][j], d);
    if (q == 0) {
#pragma unroll
        for (int s = 0; s < 4; ++s)
            *(float4*)(sm + T_SHP + (w * 32 + q4 + 8 * s) * 16) =
                make_float4(lg[s][0], lg[s][1], lg[s][2], lg[s][3]);
    }
    __syncthreads();

    if (tid < 128) {
        const float* msc = (const float*)(sm + T_MSC);
        int rg = tid >> 5, lr = tid & 31, h = tid & 15;
        float l0 = msc[0], l1 = msc[1], l2 = msc[2], l3 = msc[3];
#pragma unroll
        for (int cg = 0; cg < 4; ++cg) {
            float4 pp = *(const float4*)(sm + T_SHP + ((rg * 4 + cg) * 32 + lr) * 16);
            l0 += pp.x; l1 += pp.y; l2 += pp.z; l3 += pp.w;
        }
        float tt = fminf(fmaxf(msc[4 + h], 0.2f), 10.f);
        float it = 1.f / tt;
        float m = fmaxf(fmaxf(l0, l1), fmaxf(l2, l3));
        float e0 = expf((l0 - m) * it), e1 = expf((l1 - m) * it);
        float e2 = expf((l2 - m) * it), e3 = expf((l3 - m) * it);
        float inv = 1.f / (e0 + e1 + e2 + e3);
        float q0 = e0 * inv, q1 = e1 * inv, q2 = e2 * inv, q3 = e3 * inv;
        q0 = fmaxf(q0, fminf(fmaxf(msc[20 + h * 4 + 0], 1e-7f), 0.1f));
        q1 = fmaxf(q1, fminf(fmaxf(msc[20 + h * 4 + 1], 1e-7f), 0.1f));
        q2 = fmaxf(q2, fminf(fmaxf(msc[20 + h * 4 + 2], 1e-7f), 0.1f));
        q3 = fmaxf(q3, fminf(fmaxf(msc[20 + h * 4 + 3], 1e-7f), 0.1f));
        inv = 1.f / (q0 + q1 + q2 + q3);
        *(float4*)&out[(size_t)(tok0 * 16 + tid) * 4] =
            make_float4(q0 * inv, q1 * inv, q2 * inv, q3 * inv);
    }
}

extern "C" void kernel_launch(void* const* d_in, const int* in_sizes, int n_in,
                              void* d_out, int out_size) {
    const float* hidden = (const float*)d_in[0];
    const float* br0    = (const float*)d_in[1];
    const float* br1    = (const float*)d_in[2];
    const float* br2    = (const float*)d_in[3];
    const float* br3    = (const float*)d_in[4];
    const float* W1     = (const float*)d_in[5];
    const float* b1     = (const float*)d_in[6];
    const float* W2     = (const float*)d_in[7];
    const float* b2     = (const float*)d_in[8];
    const float* epsf   = (const float*)d_in[9];
    const float* temp   = (const float*)d_in[10];
    float* out = (float*)d_out;

    cudaFuncSetAttribute(k_hid,  cudaFuncAttributeMaxDynamicSharedMemorySize, H_SMEM);
    cudaFuncSetAttribute(k_tail, cudaFuncAttributeMaxDynamicSharedMemorySize, T_SMEM);

    k_prep<<<173, 128>>>(W1);
    k_hid<<<128, 256, H_SMEM>>>(hidden);
    k_tail<<<512, 512, T_SMEM>>>(br0, br1, br2, br3, b1, W2, b2, epsf, temp, out);
}

// round 7
// speedup vs baseline: 1.0535x; 1.0535x over previous
#include <cuda_runtime.h>
#include <cuda_bf16.h>
#include <math.h>

typedef unsigned int uint32;

// ============================================================================
// HeadGroupedFusionGate, mma.sync bf16 3-term split (x*w ~ xh*wh + xl*wh + xh*wl).
// R7: B operand loaded per-fragment via LDG.32 from TRANSPOSED k-contiguous
//     weight tiles (L1-resident) — no B smem, no cp.async. A via proven
//     smem-staged path. 32x32 warp tiles.
// Layout: g_Wt{h,l}[chunk][n=128][k=72 pad] bf16, row stride 144 B.
//   chunks 0..15 = hidden K, 16..19 = tail branches, 20 = statw colsums.
// ============================================================================

__device__ uint4 g_Wth[21 * 128 * 9];   // 144 B per n-row, 16B-aligned
__device__ uint4 g_Wtl[21 * 128 * 9];
__device__ float g_hidc[4][4096 * 128]; // 4-way K-split partials

// ---- PTX helpers ----
__device__ __forceinline__ uint32 smem_u32(const void* p) {
    uint32 a;
    asm("{ .reg .u64 t; cvta.to.shared.u64 t, %1; cvt.u32.u64 %0, t; }" : "=r"(a) : "l"(p));
    return a;
}
__device__ __forceinline__ void ldsm4(uint32* r, uint32 a) {
    asm volatile("ldmatrix.sync.aligned.m8n8.x4.shared.b16 {%0,%1,%2,%3}, [%4];"
        : "=r"(r[0]), "=r"(r[1]), "=r"(r[2]), "=r"(r[3]) : "r"(a));
}
__device__ __forceinline__ void mma16816(float* d, const uint32* a, uint32 b0, uint32 b1) {
    asm volatile("mma.sync.aligned.m16n8k16.row.col.f32.bf16.bf16.f32 "
        "{%0,%1,%2,%3}, {%4,%5,%6,%7}, {%8,%9}, {%0,%1,%2,%3};"
        : "+f"(d[0]), "+f"(d[1]), "+f"(d[2]), "+f"(d[3])
        : "r"(a[0]), "r"(a[1]), "r"(a[2]), "r"(a[3]), "r"(b0), "r"(b1));
}
__device__ __forceinline__ void cvtpair(float v0, float v1, uint32& h, uint32& l) {
    __nv_bfloat162 hp = __floats2bfloat162_rn(v0, v1);
    h = *(uint32*)&hp;
    float r0 = v0 - __bfloat162float(hp.x);
    float r1 = v1 - __bfloat162float(hp.y);
    __nv_bfloat162 lp = __floats2bfloat162_rn(r0, r1);
    l = *(uint32*)&lp;
}

// warp tile 32 rows x 32 cols; NK k16 steps; A from smem (stride SA, ldsm),
// B fragments directly from global transposed tiles (Bh/Bl pre-offset by cb*144).
template <int NK, int SA>
__device__ __forceinline__ void mma_chunk(float (&acc)[2][4][4],
                                          uint32 Ah, uint32 Al,
                                          const char* __restrict__ Bh,
                                          const char* __restrict__ Bl, int lane) {
    uint32 aoff = (uint32)((lane & 15) * SA + (lane >> 4) * 16);
    const int nb = lane >> 2, kq = 2 * (lane & 3);
#pragma unroll
    for (int k = 0; k < NK; ++k) {
        uint32 ah[2][4], al[2][4];
        ldsm4(ah[0], Ah + aoff + k * 32);
        ldsm4(ah[1], Ah + 16 * SA + aoff + k * 32);
        ldsm4(al[0], Al + aoff + k * 32);
        ldsm4(al[1], Al + 16 * SA + aoff + k * 32);
        int kk = k * 16 + kq;
#pragma unroll
        for (int nt = 0; nt < 4; ++nt) {
            const char* ph = Bh + (nb + nt * 8) * 144 + kk * 2;
            const char* pl = Bl + (nb + nt * 8) * 144 + kk * 2;
            uint32 bh0 = *(const uint32*)ph, bh1 = *(const uint32*)(ph + 16);
            uint32 bl0 = *(const uint32*)pl, bl1 = *(const uint32*)(pl + 16);
#pragma unroll
            for (int m = 0; m < 2; ++m) {
                mma16816(acc[m][nt], ah[m], bh0, bh1);
                mma16816(acc[m][nt], al[m], bh0, bh1);
                mma16816(acc[m][nt], ah[m], bl0, bl1);
            }
        }
    }
}

// ============================================================================
// k_prep: grid 33. b<20: transpose one 64x128 W1 block -> g_Wt (via smem).
//         20..31: statw colsum k = b-20. 32: zero chunk20 k=12..15.
// ============================================================================
__global__ void __launch_bounds__(128) k_prep(const float* __restrict__ W1) {
    int b = blockIdx.x, tid = threadIdx.x;
    char* WH = (char*)g_Wth;
    char* WL = (char*)g_Wtl;
    if (b < 20) {
        __shared__ float ts[64 * 132];
        int row0 = (b < 16) ? b * 64 : 1792 + (b - 16) * 64;
#pragma unroll
        for (int i = 0; i < 16; ++i) {
            int u = tid + 128 * i;            // 0..2047 float4
            int r = u >> 5, seg = u & 31;
            *(float4*)&ts[r * 132 + seg * 4] = ((const float4*)W1)[(size_t)(row0 + r) * 32 + seg];
        }
        __syncthreads();
        int n = tid;
        char* ph = WH + (size_t)(b * 128 + n) * 144;
        char* pl = WL + (size_t)(b * 128 + n) * 144;
#pragma unroll
        for (int g = 0; g < 8; ++g) {
            uint4 H, L;
            uint32* Hp = (uint32*)&H; uint32* Lp = (uint32*)&L;
#pragma unroll
            for (int t = 0; t < 4; ++t) {
                int k = g * 8 + t * 2;
                cvtpair(ts[k * 132 + n], ts[(k + 1) * 132 + n], Hp[t], Lp[t]);
            }
            *(uint4*)(ph + g * 16) = H;
            *(uint4*)(pl + g * 16) = L;
        }
    } else if (b < 32) {
        int k = b - 20;
        int row0 = 1024 + (k / 3) * 192 + (k % 3) * 64;
        float s = 0.f;
#pragma unroll 8
        for (int d = 0; d < 64; ++d) s += W1[(size_t)(row0 + d) * 128 + tid];
        __nv_bfloat16 h = __float2bfloat16_rn(s);
        *(__nv_bfloat16*)(WH + (size_t)(20 * 128 + tid) * 144 + 2 * k) = h;
        *(__nv_bfloat16*)(WL + (size_t)(20 * 128 + tid) * 144 + 2 * k) =
            __float2bfloat16_rn(s - __bfloat162float(h));
    } else {
        __nv_bfloat16 z = __float2bfloat16_rn(0.f);
#pragma unroll
        for (int k = 12; k < 16; ++k) {
            *(__nv_bfloat16*)(WH + (size_t)(20 * 128 + tid) * 144 + 2 * k) = z;
            *(__nv_bfloat16*)(WL + (size_t)(20 * 128 + tid) * 144 + 2 * k) = z;
        }
    }
}

// ============================================================================
// k_hid: grid 256 (bid>>2 = 64-token group, bid&3 = K quarter of 4 chunks).
//        256 thr = 8 warps: rowg=w>>2 (2x32 rows), colg=w&3 (4x32 cols).
// smem: Ahi 0 (64x144=9216), Alo 9216. Total 18432.
// ============================================================================
#define H2_ALO 9216
#define H2_SMEM 18432

__global__ void __launch_bounds__(256) k_hid(const float* __restrict__ hidden) {
    extern __shared__ char sm[];
    uint32 sb = smem_u32(sm);
    int tid = threadIdx.x, lane = tid & 31, w = tid >> 5;
    int rowg = w >> 2, colg = w & 3;
    int rb = rowg * 32, cb = colg * 32;
    int tg = blockIdx.x >> 2, kq = blockIdx.x & 3;
    int tok0 = tg * 64;

    float acc[2][4][4];
#pragma unroll
    for (int m = 0; m < 2; ++m)
#pragma unroll
        for (int n = 0; n < 4; ++n)
#pragma unroll
            for (int i = 0; i < 4; ++i) acc[m][n][i] = 0.f;

    for (int p = 0; p < 4; ++p) {
        int c = kq * 4 + p;
        __syncthreads();
        float4 f[4];
        const float4* src = (const float4*)hidden;
#pragma unroll
        for (int i = 0; i < 4; ++i) {
            int u = tid + 256 * i;
            int r = u >> 4, seg = u & 15;
            f[i] = src[(size_t)(tok0 + r) * 256 + c * 16 + seg];
        }
#pragma unroll
        for (int i = 0; i < 4; ++i) {
            int u = tid + 256 * i;
            int r = u >> 4, seg = u & 15;
            uint32 h0, l0, h1, l1;
            cvtpair(f[i].x, f[i].y, h0, l0);
            cvtpair(f[i].z, f[i].w, h1, l1);
            *(uint2*)(sm + r * 144 + seg * 8) = make_uint2(h0, h1);
            *(uint2*)(sm + H2_ALO + r * 144 + seg * 8) = make_uint2(l0, l1);
        }
        __syncthreads();
        const char* BH = (const char*)g_Wth + (size_t)c * 18432 + cb * 144;
        const char* BL = (const char*)g_Wtl + (size_t)c * 18432 + cb * 144;
        mma_chunk<4, 144>(acc, sb + rb * 144, sb + H2_ALO + rb * 144, BH, BL, lane);
    }

    float* dst = g_hidc[kq];
    int q4 = lane >> 2, q = lane & 3;
#pragma unroll
    for (int m = 0; m < 2; ++m)
#pragma unroll
        for (int nt = 0; nt < 4; ++nt) {
            int c0 = cb + nt * 8 + 2 * q;
            int rA = rb + 16 * m + q4;
            *(float2*)&dst[(size_t)(tok0 + rA) * 128 + c0] = make_float2(acc[m][nt][0], acc[m][nt][1]);
            *(float2*)&dst[(size_t)(tok0 + rA + 8) * 128 + c0] = make_float2(acc[m][nt][2], acc[m][nt][3]);
        }
}

// ============================================================================
// k_tail: grid 512, 512 thr = 16 warps: rowg=w>>2 (4x32 rows), colg=w&3 (4x32).
// CTA = 8 tokens x 16 heads = 128 rows.
// smem (bytes): AHI 0 (18432) | ALO 18432 | ASH 36864 (128x48) | ASL 43008 |
//               HID 49152 (4KB) | W2S 53248 (2KB) | SHP 55296 (8KB) | MSC 63488
// ============================================================================
#define T2_ALO 18432
#define T2_ASH 36864
#define T2_ASL 43008
#define T2_HID 49152
#define T2_W2S 53248
#define T2_SHP 55296
#define T2_MSC 63488
#define T2_SMEM 64000

__global__ void __launch_bounds__(512) k_tail(
    const float* __restrict__ br0, const float* __restrict__ br1,
    const float* __restrict__ br2, const float* __restrict__ br3,
    const float* __restrict__ b1, const float* __restrict__ W2,
    const float* __restrict__ b2, const float* __restrict__ epsf,
    const float* __restrict__ temp, float* __restrict__ out) {
    extern __shared__ char sm[];
    uint32 sb = smem_u32(sm);
    int tid = threadIdx.x, lane = tid & 31, w = tid >> 5;
    int rowg = w >> 2, colg = w & 3;
    int rb = rowg * 32, cb = colg * 32;
    int q4 = lane >> 2, q = lane & 3;
    int tok0 = blockIdx.x * 8;
    const float* brs[4] = {br0, br1, br2, br3};

    // prologue: epilogue staging + stat-A-tile zero pad (k 12..15)
    if (tid < 256) {
        int row = tid >> 5, c4 = tid & 31;
        float4 a0 = *(const float4*)&g_hidc[0][(size_t)(tok0 + row) * 128 + c4 * 4];
        float4 a1 = *(const float4*)&g_hidc[1][(size_t)(tok0 + row) * 128 + c4 * 4];
        float4 a2 = *(const float4*)&g_hidc[2][(size_t)(tok0 + row) * 128 + c4 * 4];
        float4 a3 = *(const float4*)&g_hidc[3][(size_t)(tok0 + row) * 128 + c4 * 4];
        float4 c = ((const float4*)b1)[c4];
        *(float4*)(sm + T2_HID + tid * 16) = make_float4(
            a0.x + a1.x + a2.x + a3.x + c.x, a0.y + a1.y + a2.y + a3.y + c.y,
            a0.z + a1.z + a2.z + a3.z + c.z, a0.w + a1.w + a2.w + a3.w + c.w);
    }
    if (tid < 128) {
        *(float4*)(sm + T2_W2S + tid * 16) = ((const float4*)W2)[tid];
        *(uint2*)(sm + T2_ASH + tid * 48 + 24) = make_uint2(0u, 0u);
        *(uint2*)(sm + T2_ASL + tid * 48 + 24) = make_uint2(0u, 0u);
    }
    {
        float* msc = (float*)(sm + T2_MSC);
        if (tid < 4)  msc[tid] = b2[tid];
        if (tid < 16) msc[4 + tid] = temp[tid];
        if (tid < 64) msc[20 + tid] = epsf[tid];
    }

    float acc[2][4][4];
#pragma unroll
    for (int m = 0; m < 2; ++m)
#pragma unroll
        for (int n = 0; n < 4; ++n)
#pragma unroll
            for (int i = 0; i < 4; ++i) acc[m][n][i] = 0.f;

    for (int p = 0; p < 5; ++p) {
        __syncthreads();                      // A tiles free (prev mma done)
        if (p < 4) {
            float4 f[4];
            const float4* src = (const float4*)brs[p];
#pragma unroll
            for (int i = 0; i < 4; ++i) f[i] = src[(size_t)tok0 * 256 + tid + 512 * i];
            // stats: each row owned by 16 consecutive lanes
#pragma unroll
            for (int i = 0; i < 4; ++i) {
                float4 v = f[i];
                int row = (tid >> 4) + 32 * i, seg = tid & 15;
                float s = v.x + v.y + v.z + v.w;
                float s2 = fmaf(v.x, v.x, fmaf(v.y, v.y, fmaf(v.z, v.z, v.w * v.w)));
                float mx = fmaxf(fmaxf(v.x, v.y), fmaxf(v.z, v.w));
#pragma unroll
                for (int d = 1; d <= 8; d <<= 1) {
                    s += __shfl_xor_sync(0xffffffffu, s, d);
                    s2 += __shfl_xor_sync(0xffffffffu, s2, d);
                    mx = fmaxf(mx, __shfl_xor_sync(0xffffffffu, mx, d));
                }
                if (seg < 3) {
                    float sval = (seg == 0) ? s * 0.015625f
                               : (seg == 1) ? sqrtf(fmaxf(s2 * 0.015625f, 1e-8f)) : mx;
                    __nv_bfloat16 h = __float2bfloat16_rn(sval);
                    *(__nv_bfloat16*)(sm + T2_ASH + row * 48 + (p * 3 + seg) * 2) = h;
                    *(__nv_bfloat16*)(sm + T2_ASL + row * 48 + (p * 3 + seg) * 2) =
                        __float2bfloat16_rn(sval - __bfloat162float(h));
                }
                uint32 h0, l0, h1, l1;
                cvtpair(v.x, v.y, h0, l0);
                cvtpair(v.z, v.w, h1, l1);
                *(uint2*)(sm + row * 144 + seg * 8) = make_uint2(h0, h1);
                *(uint2*)(sm + T2_ALO + row * 144 + seg * 8) = make_uint2(l0, l1);
            }
            __syncthreads();
            const char* BH = (const char*)g_Wth + (size_t)(16 + p) * 18432 + cb * 144;
            const char* BL = (const char*)g_Wtl + (size_t)(16 + p) * 18432 + cb * 144;
            mma_chunk<4, 144>(acc, sb + rb * 144, sb + T2_ALO + rb * 144, BH, BL, lane);
        } else {
            const char* BH = (const char*)g_Wth + (size_t)20 * 18432 + cb * 144;
            const char* BL = (const char*)g_Wtl + (size_t)20 * 18432 + cb * 144;
            mma_chunk<1, 48>(acc, sb + T2_ASH + rb * 48, sb + T2_ASL + rb * 48, BH, BL, lane);
        }
    }

    // ---- epilogue: gelu + W2 partial logits ----
    float lg[4][4];
#pragma unroll
    for (int s = 0; s < 4; ++s)
#pragma unroll
        for (int j = 0; j < 4; ++j) lg[s][j] = 0.f;

#pragma unroll
    for (int m = 0; m < 2; ++m) {
        int tokc = rowg * 2 + m;
#pragma unroll
        for (int nt = 0; nt < 4; ++nt) {
            int c0 = cb + nt * 8 + 2 * q;
            float2 hv = *(const float2*)(sm + T2_HID + (tokc * 128 + c0) * 4);
            float4 wa = *(const float4*)(sm + T2_W2S + c0 * 16);
            float4 wb = *(const float4*)(sm + T2_W2S + (c0 + 1) * 16);
            float v0 = acc[m][nt][0] + hv.x, v1 = acc[m][nt][1] + hv.y;
            float v2 = acc[m][nt][2] + hv.x, v3 = acc[m][nt][3] + hv.y;
            float g0 = v0 * normcdff(v0), g1 = v1 * normcdff(v1);
            float g2 = v2 * normcdff(v2), g3 = v3 * normcdff(v3);
            lg[2 * m][0] = fmaf(g0, wa.x, fmaf(g1, wb.x, lg[2 * m][0]));
            lg[2 * m][1] = fmaf(g0, wa.y, fmaf(g1, wb.y, lg[2 * m][1]));
            lg[2 * m][2] = fmaf(g0, wa.z, fmaf(g1, wb.z, lg[2 * m][2]));
            lg[2 * m][3] = fmaf(g0, wa.w, fmaf(g1, wb.w, lg[2 * m][3]));
            lg[2 * m + 1][0] = fmaf(g2, wa.x, fmaf(g3, wb.x, lg[2 * m + 1][0]));
            lg[2 * m + 1][1] = fmaf(g2, wa.y, fmaf(g3, wb.y, lg[2 * m + 1][1]));
            lg[2 * m + 1][2] = fmaf(g2, wa.z, fmaf(g3, wb.z, lg[2 * m + 1][2]));
            lg[2 * m + 1][3] = fmaf(g2, wa.w, fmaf(g3, wb.w, lg[2 * m + 1][3]));
        }
    }
#pragma unroll
    for (int d = 1; d <= 2; d <<= 1)
#pragma unroll
        for (int s = 0; s < 4; ++s)
#pragma unroll
            for (int j = 0; j < 4; ++j)
                lg[s][j] += __shfl_xor_sync(0xffffffffu, lg[s][j], d);
    if (q == 0) {
#pragma unroll
        for (int s = 0; s < 4; ++s)
            *(float4*)(sm + T2_SHP + (w * 32 + q4 + 8 * s) * 16) =
                make_float4(lg[s][0], lg[s][1], lg[s][2], lg[s][3]);
    }
    __syncthreads();

    if (tid < 128) {
        const float* msc = (const float*)(sm + T2_MSC);
        int rg = tid >> 5, lr = tid & 31, h = tid & 15;
        float l0 = msc[0], l1 = msc[1], l2 = msc[2], l3 = msc[3];
#pragma unroll
        for (int cg = 0; cg < 4; ++cg) {
            float4 pp = *(const float4*)(sm + T2_SHP + ((rg * 4 + cg) * 32 + lr) * 16);
            l0 += pp.x; l1 += pp.y; l2 += pp.z; l3 += pp.w;
        }
        float tt = fminf(fmaxf(msc[4 + h], 0.2f), 10.f);
        float it = 1.f / tt;
        float m = fmaxf(fmaxf(l0, l1), fmaxf(l2, l3));
        float e0 = expf((l0 - m) * it), e1 = expf((l1 - m) * it);
        float e2 = expf((l2 - m) * it), e3 = expf((l3 - m) * it);
        float inv = 1.f / (e0 + e1 + e2 + e3);
        float q0 = e0 * inv, q1 = e1 * inv, q2 = e2 * inv, q3 = e3 * inv;
        q0 = fmaxf(q0, fminf(fmaxf(msc[20 + h * 4 + 0], 1e-7f), 0.1f));
        q1 = fmaxf(q1, fminf(fmaxf(msc[20 + h * 4 + 1], 1e-7f), 0.1f));
        q2 = fmaxf(q2, fminf(fmaxf(msc[20 + h * 4 + 2], 1e-7f), 0.1f));
        q3 = fmaxf(q3, fminf(fmaxf(msc[20 + h * 4 + 3], 1e-7f), 0.1f));
        inv = 1.f / (q0 + q1 + q2 + q3);
        *(float4*)&out[(size_t)(tok0 * 16 + tid) * 4] =
            make_float4(q0 * inv, q1 * inv, q2 * inv, q3 * inv);
    }
}

extern "C" void kernel_launch(void* const* d_in, const int* in_sizes, int n_in,
                              void* d_out, int out_size) {
    const float* hidden = (const float*)d_in[0];
    const float* br0    = (const float*)d_in[1];
    const float* br1    = (const float*)d_in[2];
    const float* br2    = (const float*)d_in[3];
    const float* br3    = (const float*)d_in[4];
    const float* W1     = (const float*)d_in[5];
    const float* b1     = (const float*)d_in[6];
    const float* W2     = (const float*)d_in[7];
    const float* b2     = (const float*)d_in[8];
    const float* epsf   = (const float*)d_in[9];
    const float* temp   = (const float*)d_in[10];
    float* out = (float*)d_out;

    cudaFuncSetAttribute(k_hid,  cudaFuncAttributeMaxDynamicSharedMemorySize, H2_SMEM);
    cudaFuncSetAttribute(k_tail, cudaFuncAttributeMaxDynamicSharedMemorySize, T2_SMEM);

    k_prep<<<33, 128>>>(W1);
    k_hid<<<256, 256, H2_SMEM>>>(hidden);
    k_tail<<<512, 512, T2_SMEM>>>(br0, br1, br2, br3, b1, W2, b2, epsf, temp, out);
}

// round 8
// speedup vs baseline: 1.2092x; 1.1479x over previous
#include <cuda_runtime.h>
#include <cuda_bf16.h>
#include <math.h>

typedef unsigned int uint32;

// ============================================================================
// HeadGroupedFusionGate, mma.sync bf16 3-term split (x*w ~ xh*wh + xl*wh + xh*wl).
// R8: B tiles delivered by cp.async.bulk (1 instr/tile, mbarrier completion),
//     A via R5's proven LDG->convert->STS path, double-buffered + pipelined.
//     R6's 32x32 warp tiling.
// Weight layout (R5): g_Wh/g_Wl[chunk][k=64][n=136 pad] bf16, 17408 B/chunk.
//   chunks 0..15 = hidden K, 16..19 = tail branches, 20 = statw colsums.
// ============================================================================

__device__ uint4 g_WhV[21 * 1088];    // 16B-aligned backing
__device__ uint4 g_WlV[21 * 1088];
__device__ float g_hidc[2][4096 * 128];

// ---- PTX helpers ----
__device__ __forceinline__ uint32 smem_u32(const void* p) {
    uint32 a;
    asm("{ .reg .u64 t; cvta.to.shared.u64 t, %1; cvt.u32.u64 %0, t; }" : "=r"(a) : "l"(p));
    return a;
}
__device__ __forceinline__ void ldsm4(uint32* r, uint32 a) {
    asm volatile("ldmatrix.sync.aligned.m8n8.x4.shared.b16 {%0,%1,%2,%3}, [%4];"
        : "=r"(r[0]), "=r"(r[1]), "=r"(r[2]), "=r"(r[3]) : "r"(a));
}
__device__ __forceinline__ void ldsm4t(uint32* r, uint32 a) {
    asm volatile("ldmatrix.sync.aligned.m8n8.x4.trans.shared.b16 {%0,%1,%2,%3}, [%4];"
        : "=r"(r[0]), "=r"(r[1]), "=r"(r[2]), "=r"(r[3]) : "r"(a));
}
__device__ __forceinline__ void mma16816(float* d, const uint32* a, uint32 b0, uint32 b1) {
    asm volatile("mma.sync.aligned.m16n8k16.row.col.f32.bf16.bf16.f32 "
        "{%0,%1,%2,%3}, {%4,%5,%6,%7}, {%8,%9}, {%0,%1,%2,%3};"
        : "+f"(d[0]), "+f"(d[1]), "+f"(d[2]), "+f"(d[3])
        : "r"(a[0]), "r"(a[1]), "r"(a[2]), "r"(a[3]), "r"(b0), "r"(b1));
}
__device__ __forceinline__ void cvtpair(float v0, float v1, uint32& h, uint32& l) {
    __nv_bfloat162 hp = __floats2bfloat162_rn(v0, v1);
    h = *(uint32*)&hp;
    float r0 = v0 - __bfloat162float(hp.x);
    float r1 = v1 - __bfloat162float(hp.y);
    __nv_bfloat162 lp = __floats2bfloat162_rn(r0, r1);
    l = *(uint32*)&lp;
}
#define MBAR_INIT(mb, n) \
    asm volatile("mbarrier.init.shared.b64 [%0], %1;" :: "r"(mb), "r"(n) : "memory")
#define MBAR_EXPECT(mb, tx) \
    asm volatile("mbarrier.arrive.expect_tx.shared.b64 _, [%0], %1;" :: "r"(mb), "r"(tx) : "memory")
__device__ __forceinline__ void bulk_cp(uint32 dst, const void* src, uint32 bytes, uint32 mb) {
    asm volatile("cp.async.bulk.shared::cta.global.mbarrier::complete_tx::bytes "
                 "[%0], [%1], %2, [%3];" :: "r"(dst), "l"(src), "r"(bytes), "r"(mb) : "memory");
}
__device__ __forceinline__ void mbar_wait(uint32 mb, uint32 parity) {
    asm volatile(
        "{\n\t.reg .pred P;\n\t"
        "W%=:\n\tmbarrier.try_wait.parity.acquire.cta.shared::cta.b64 P, [%0], %1, 0x989680;\n\t"
        "@P bra.uni D%=;\n\tbra.uni W%=;\n\tD%=:\n\t}"
        :: "r"(mb), "r"(parity) : "memory");
}

// warp tile 32 rows x 32 cols; NK k16 steps; A and B both from smem via ldmatrix.
// Ah/Al pre-offset by rb; Bh/Bl pre-offset by colg*64. B rows = 272 B, k-stride 4352.
template <int NK, int SA>
__device__ __forceinline__ void mma_chunk(float (&acc)[2][4][4],
                                          uint32 Ah, uint32 Al,
                                          uint32 Bh, uint32 Bl, int lane) {
    uint32 aoff = (uint32)((lane & 15) * SA + (lane >> 4) * 16);
    uint32 boff = (uint32)(((lane & 7) + ((lane >> 3) & 1) * 8) * 272 + ((lane >> 4) & 1) * 16);
#pragma unroll
    for (int k = 0; k < NK; ++k) {
        uint32 ah[2][4], al[2][4];
        ldsm4(ah[0], Ah + aoff + k * 32);
        ldsm4(ah[1], Ah + 16 * SA + aoff + k * 32);
        ldsm4(al[0], Al + aoff + k * 32);
        ldsm4(al[1], Al + 16 * SA + aoff + k * 32);
        uint32 bh0[4], bh1[4], bl0[4], bl1[4];
        uint32 bb = boff + k * 4352;
        ldsm4t(bh0, Bh + bb); ldsm4t(bh1, Bh + bb + 32);
        ldsm4t(bl0, Bl + bb); ldsm4t(bl1, Bl + bb + 32);
#pragma unroll
        for (int m = 0; m < 2; ++m) {
            mma16816(acc[m][0], ah[m], bh0[0], bh0[1]);
            mma16816(acc[m][1], ah[m], bh0[2], bh0[3]);
            mma16816(acc[m][2], ah[m], bh1[0], bh1[1]);
            mma16816(acc[m][3], ah[m], bh1[2], bh1[3]);
            mma16816(acc[m][0], al[m], bh0[0], bh0[1]);
            mma16816(acc[m][1], al[m], bh0[2], bh0[3]);
            mma16816(acc[m][2], al[m], bh1[0], bh1[1]);
            mma16816(acc[m][3], al[m], bh1[2], bh1[3]);
            mma16816(acc[m][0], ah[m], bl0[0], bl0[1]);
            mma16816(acc[m][1], ah[m], bl0[2], bl0[3]);
            mma16816(acc[m][2], ah[m], bl1[0], bl1[1]);
            mma16816(acc[m][3], ah[m], bl1[2], bl1[3]);
        }
    }
}

// ============================================================================
// k_prep (R5 version): grid 173.
// ============================================================================
__global__ void __launch_bounds__(128) k_prep(const float* __restrict__ W1) {
    int b = blockIdx.x, tid = threadIdx.x;
    __nv_bfloat16* Wh = (__nv_bfloat16*)g_WhV;
    __nv_bfloat16* Wl = (__nv_bfloat16*)g_WlV;
    if (b < 160) {
        int rr0 = b * 8;
#pragma unroll
        for (int j = 0; j < 8; ++j) {
            int rr = rr0 + j;
            int c = rr >> 6, k = rr & 63;
            int row = (c < 16) ? c * 64 + k : 1792 + (c - 16) * 64 + k;
            float v = W1[(size_t)row * 128 + tid];
            __nv_bfloat16 h = __float2bfloat16_rn(v);
            Wh[rr * 136 + tid] = h;
            Wl[rr * 136 + tid] = __float2bfloat16_rn(v - __bfloat162float(h));
        }
    } else if (b < 172) {
        int k = b - 160;
        int row0 = 1024 + (k / 3) * 192 + (k % 3) * 64;
        float s = 0.f;
#pragma unroll 8
        for (int d = 0; d < 64; ++d) s += W1[(size_t)(row0 + d) * 128 + tid];
        __nv_bfloat16 h = __float2bfloat16_rn(s);
        Wh[(1280 + k) * 136 + tid] = h;
        Wl[(1280 + k) * 136 + tid] = __float2bfloat16_rn(s - __bfloat162float(h));
    } else {
        __nv_bfloat16 z = __float2bfloat16_rn(0.f);
#pragma unroll
        for (int k = 12; k < 16; ++k) {
            Wh[(1280 + k) * 136 + tid] = z;
            Wl[(1280 + k) * 136 + tid] = z;
        }
    }
}

// ============================================================================
// k_hid: grid 128 (bid>>1 = 64-token group, bid&1 = K half of 8 chunks).
// 256 thr = 8 warps: rowg=w>>2 (2x32 rows), colg=w&3 (4x32 cols).
// smem: Abuf[2] @0 (each: AHI 9216 + ALO 9216), B[2] @36864 (each 34816),
//       mbar @106496. Total 106512.
// ============================================================================
#define H_BB   36864
#define H_MB   106496
#define H_SMEM 106512

__global__ void __launch_bounds__(256, 1) k_hid(const float* __restrict__ hidden) {
    extern __shared__ char sm[];
    uint32 sb = smem_u32(sm);
    int tid = threadIdx.x, lane = tid & 31, w = tid >> 5;
    int rb = (w >> 2) * 32, cb = (w & 3) * 32;
    int tg = blockIdx.x >> 1, khalf = blockIdx.x & 1;
    int tok0 = tg * 64;
    const char* WhB = (const char*)g_WhV;
    const char* WlB = (const char*)g_WlV;

    if (tid == 0) { MBAR_INIT(sb + H_MB, 1); MBAR_INIT(sb + H_MB + 8, 1); }
    __syncthreads();

    float acc[2][4][4];
#pragma unroll
    for (int m = 0; m < 2; ++m)
#pragma unroll
        for (int n = 0; n < 4; ++n)
#pragma unroll
            for (int i = 0; i < 4; ++i) acc[m][n][i] = 0.f;

    uint32 ph0 = 0, ph1 = 0;
    // prologue: bulk chunk0 + A(0) LDG
    if (tid == 0) {
        int c = khalf * 8;
        MBAR_EXPECT(sb + H_MB, 34816u);
        bulk_cp(sb + H_BB, WhB + (size_t)c * 17408, 17408u, sb + H_MB);
        bulk_cp(sb + H_BB + 17408, WlB + (size_t)c * 17408, 17408u, sb + H_MB);
    }
    float4 f[4];
    {
        const float4* src = (const float4*)hidden;
        int c = khalf * 8;
#pragma unroll
        for (int i = 0; i < 4; ++i) {
            int u = tid + 256 * i;
            f[i] = src[(size_t)(tok0 + (u >> 4)) * 256 + c * 16 + (u & 15)];
        }
    }

    for (int p = 0; p < 8; ++p) {
        int ab = (p & 1) * 18432;
        // STS A(p)
#pragma unroll
        for (int i = 0; i < 4; ++i) {
            int u = tid + 256 * i;
            int row = u >> 4, seg = u & 15;
            uint32 h0, l0, h1, l1;
            cvtpair(f[i].x, f[i].y, h0, l0);
            cvtpair(f[i].z, f[i].w, h1, l1);
            *(uint2*)(sm + ab + row * 144 + seg * 8) = make_uint2(h0, h1);
            *(uint2*)(sm + ab + 9216 + row * 144 + seg * 8) = make_uint2(l0, l1);
        }
        if (p < 7) {  // LDG A(p+1)
            const float4* src = (const float4*)hidden;
            int c = khalf * 8 + p + 1;
#pragma unroll
            for (int i = 0; i < 4; ++i) {
                int u = tid + 256 * i;
                f[i] = src[(size_t)(tok0 + (u >> 4)) * 256 + c * 16 + (u & 15)];
            }
        }
        __syncthreads();
        if (p < 7 && tid == 0) {   // bulk B(p+1) into buf (p+1)&1 (free: mma(p-1) done)
            int c = khalf * 8 + p + 1;
            uint32 bbuf = sb + H_BB + ((p + 1) & 1) * 34816;
            uint32 mb = sb + H_MB + ((p + 1) & 1) * 8;
            MBAR_EXPECT(mb, 34816u);
            bulk_cp(bbuf, WhB + (size_t)c * 17408, 17408u, mb);
            bulk_cp(bbuf + 17408, WlB + (size_t)c * 17408, 17408u, mb);
        }
        if ((p & 1) == 0) { mbar_wait(sb + H_MB, ph0); ph0 ^= 1; }
        else              { mbar_wait(sb + H_MB + 8, ph1); ph1 ^= 1; }
        uint32 bbase = sb + H_BB + (p & 1) * 34816 + cb * 2;  // colg*64 bytes
        mma_chunk<4, 144>(acc, sb + ab + rb * 144, sb + ab + 9216 + rb * 144,
                          bbase, bbase + 17408, lane);
    }

    float* dst = g_hidc[khalf];
    int q4 = lane >> 2, q = lane & 3;
#pragma unroll
    for (int m = 0; m < 2; ++m)
#pragma unroll
        for (int nt = 0; nt < 4; ++nt) {
            int c0 = cb + nt * 8 + 2 * q;
            int rA = rb + 16 * m + q4;
            *(float2*)&dst[(size_t)(tok0 + rA) * 128 + c0] = make_float2(acc[m][nt][0], acc[m][nt][1]);
            *(float2*)&dst[(size_t)(tok0 + rA + 8) * 128 + c0] = make_float2(acc[m][nt][2], acc[m][nt][3]);
        }
}

// ============================================================================
// k_tail: grid 512, 512 thr = 16 warps: rowg=w>>2 (4x32 rows), colg=w&3.
// CTA = 8 tokens x 16 heads = 128 rows. Chunks p=0..3 branches, p=4 stats.
// smem: Abuf[2] @0 (each: AHI 18432 + ALO 18432) -> 73728
//       B[2] @73728 (34816 each) -> 143360
//       ASH @143360 (6144), ASL @149504 -> 155648
//       HID @155648 (4096), W2S @159744 (2048), SHP @161792 (8192),
//       MSC @169984 (512), MBAR @170496 (16). Total 170512.
// ============================================================================
#define T_BB   73728
#define T_ASH  143360
#define T_ASL  149504
#define T_HID  155648
#define T_W2S  159744
#define T_SHP  161792
#define T_MSC  169984
#define T_MB   170496
#define T_SMEM 170512

__global__ void __launch_bounds__(512, 1) k_tail(
    const float* __restrict__ br0, const float* __restrict__ br1,
    const float* __restrict__ br2, const float* __restrict__ br3,
    const float* __restrict__ b1, const float* __restrict__ W2,
    const float* __restrict__ b2, const float* __restrict__ epsf,
    const float* __restrict__ temp, float* __restrict__ out) {
    extern __shared__ char sm[];
    uint32 sb = smem_u32(sm);
    int tid = threadIdx.x, lane = tid & 31, w = tid >> 5;
    int rowg = w >> 2, colg = w & 3;
    int rb = rowg * 32, cb = colg * 32;
    int q4 = lane >> 2, q = lane & 3;
    int tok0 = blockIdx.x * 8;
    const float* brs[4] = {br0, br1, br2, br3};
    const char* WhB = (const char*)g_WhV;
    const char* WlB = (const char*)g_WlV;

    if (tid == 0) { MBAR_INIT(sb + T_MB, 1); MBAR_INIT(sb + T_MB + 8, 1); }
    // prologue staging
    if (tid < 256) {
        int row = tid >> 5, c4 = tid & 31;
        float4 a0 = *(const float4*)&g_hidc[0][(size_t)(tok0 + row) * 128 + c4 * 4];
        float4 a1 = *(const float4*)&g_hidc[1][(size_t)(tok0 + row) * 128 + c4 * 4];
        float4 c = ((const float4*)b1)[c4];
        *(float4*)(sm + T_HID + tid * 16) = make_float4(
            a0.x + a1.x + c.x, a0.y + a1.y + c.y, a0.z + a1.z + c.z, a0.w + a1.w + c.w);
    }
    if (tid < 128) {
        *(float4*)(sm + T_W2S + tid * 16) = ((const float4*)W2)[tid];
        *(uint2*)(sm + T_ASH + tid * 48 + 24) = make_uint2(0u, 0u);
        *(uint2*)(sm + T_ASL + tid * 48 + 24) = make_uint2(0u, 0u);
    }
    {
        float* msc = (float*)(sm + T_MSC);
        if (tid < 4)  msc[tid] = b2[tid];
        if (tid < 16) msc[4 + tid] = temp[tid];
        if (tid < 64) msc[20 + tid] = epsf[tid];
    }
    __syncthreads();

    float acc[2][4][4];
#pragma unroll
    for (int m = 0; m < 2; ++m)
#pragma unroll
        for (int n = 0; n < 4; ++n)
#pragma unroll
            for (int i = 0; i < 4; ++i) acc[m][n][i] = 0.f;

    uint32 ph0 = 0, ph1 = 0;
    if (tid == 0) {    // bulk chunk0 (branch 0 weights)
        MBAR_EXPECT(sb + T_MB, 34816u);
        bulk_cp(sb + T_BB, WhB + (size_t)16 * 17408, 17408u, sb + T_MB);
        bulk_cp(sb + T_BB + 17408, WlB + (size_t)16 * 17408, 17408u, sb + T_MB);
    }
    float4 f[4];
    {
        const float4* src = (const float4*)brs[0] + (size_t)tok0 * 256;
#pragma unroll
        for (int i = 0; i < 4; ++i) f[i] = src[tid + 512 * i];
    }

    for (int p = 0; p < 5; ++p) {
        int ab = (p & 1) * 36864;
        if (p < 4) {
            // stats + STS A(p)
#pragma unroll
            for (int i = 0; i < 4; ++i) {
                float4 v = f[i];
                int row = (tid >> 4) + 32 * i, seg = tid & 15;
                float s = v.x + v.y + v.z + v.w;
                float s2 = fmaf(v.x, v.x, fmaf(v.y, v.y, fmaf(v.z, v.z, v.w * v.w)));
                float mx = fmaxf(fmaxf(v.x, v.y), fmaxf(v.z, v.w));
#pragma unroll
                for (int d = 1; d <= 8; d <<= 1) {
                    s += __shfl_xor_sync(0xffffffffu, s, d);
                    s2 += __shfl_xor_sync(0xffffffffu, s2, d);
                    mx = fmaxf(mx, __shfl_xor_sync(0xffffffffu, mx, d));
                }
                if (seg < 3) {
                    float sval = (seg == 0) ? s * 0.015625f
                               : (seg == 1) ? sqrtf(fmaxf(s2 * 0.015625f, 1e-8f)) : mx;
                    __nv_bfloat16 h = __float2bfloat16_rn(sval);
                    *(__nv_bfloat16*)(sm + T_ASH + row * 48 + (p * 3 + seg) * 2) = h;
                    *(__nv_bfloat16*)(sm + T_ASL + row * 48 + (p * 3 + seg) * 2) =
                        __float2bfloat16_rn(sval - __bfloat162float(h));
                }
                uint32 h0, l0, h1, l1;
                cvtpair(v.x, v.y, h0, l0);
                cvtpair(v.z, v.w, h1, l1);
                *(uint2*)(sm + ab + row * 144 + seg * 8) = make_uint2(h0, h1);
                *(uint2*)(sm + ab + 18432 + row * 144 + seg * 8) = make_uint2(l0, l1);
            }
            if (p < 3) {  // LDG A(p+1)
                const float4* src = (const float4*)brs[p + 1] + (size_t)tok0 * 256;
#pragma unroll
                for (int i = 0; i < 4; ++i) f[i] = src[tid + 512 * i];
            }
        }
        __syncthreads();
        if (p < 4 && tid == 0) {   // bulk B(p+1)
            int chunk = (p + 1 < 4) ? 16 + p + 1 : 20;
            uint32 bytes = (p + 1 < 4) ? 17408u : 4352u;
            uint32 bbuf = sb + T_BB + ((p + 1) & 1) * 34816;
            uint32 mb = sb + T_MB + ((p + 1) & 1) * 8;
            MBAR_EXPECT(mb, bytes * 2);
            bulk_cp(bbuf, WhB + (size_t)chunk * 17408, bytes, mb);
            bulk_cp(bbuf + 17408, WlB + (size_t)chunk * 17408, bytes, mb);
        }
        if ((p & 1) == 0) { mbar_wait(sb + T_MB, ph0); ph0 ^= 1; }
        else              { mbar_wait(sb + T_MB + 8, ph1); ph1 ^= 1; }
        uint32 bbase = sb + T_BB + (p & 1) * 34816 + cb * 2;
        if (p < 4)
            mma_chunk<4, 144>(acc, sb + ab + rb * 144, sb + ab + 18432 + rb * 144,
                              bbase, bbase + 17408, lane);
        else
            mma_chunk<1, 48>(acc, sb + T_ASH + rb * 48, sb + T_ASL + rb * 48,
                             bbase, bbase + 17408, lane);
    }

    // ---- epilogue: gelu + W2 partial logits ----
    float lg[4][4];
#pragma unroll
    for (int s = 0; s < 4; ++s)
#pragma unroll
        for (int j = 0; j < 4; ++j) lg[s][j] = 0.f;
#pragma unroll
    for (int m = 0; m < 2; ++m) {
        int tokc = rowg * 2 + m;
#pragma unroll
        for (int nt = 0; nt < 4; ++nt) {
            int c0 = cb + nt * 8 + 2 * q;
            float2 hv = *(const float2*)(sm + T_HID + (tokc * 128 + c0) * 4);
            float4 wa = *(const float4*)(sm + T_W2S + c0 * 16);
            float4 wb = *(const float4*)(sm + T_W2S + (c0 + 1) * 16);
            float v0 = acc[m][nt][0] + hv.x, v1 = acc[m][nt][1] + hv.y;
            float v2 = acc[m][nt][2] + hv.x, v3 = acc[m][nt][3] + hv.y;
            float g0 = v0 * normcdff(v0), g1 = v1 * normcdff(v1);
            float g2 = v2 * normcdff(v2), g3 = v3 * normcdff(v3);
            lg[2 * m][0] = fmaf(g0, wa.x, fmaf(g1, wb.x, lg[2 * m][0]));
            lg[2 * m][1] = fmaf(g0, wa.y, fmaf(g1, wb.y, lg[2 * m][1]));
            lg[2 * m][2] = fmaf(g0, wa.z, fmaf(g1, wb.z, lg[2 * m][2]));
            lg[2 * m][3] = fmaf(g0, wa.w, fmaf(g1, wb.w, lg[2 * m][3]));
            lg[2 * m + 1][0] = fmaf(g2, wa.x, fmaf(g3, wb.x, lg[2 * m + 1][0]));
            lg[2 * m + 1][1] = fmaf(g2, wa.y, fmaf(g3, wb.y, lg[2 * m + 1][1]));
            lg[2 * m + 1][2] = fmaf(g2, wa.z, fmaf(g3, wb.z, lg[2 * m + 1][2]));
            lg[2 * m + 1][3] = fmaf(g2, wa.w, fmaf(g3, wb.w, lg[2 * m + 1][3]));
        }
    }
#pragma unroll
    for (int d = 1; d <= 2; d <<= 1)
#pragma unroll
        for (int s = 0; s < 4; ++s)
#pragma unroll
            for (int j = 0; j < 4; ++j)
                lg[s][j] += __shfl_xor_sync(0xffffffffu, lg[s][j], d);
    if (q == 0) {
#pragma unroll
        for (int s = 0; s < 4; ++s)
            *(float4*)(sm + T_SHP + (w * 32 + q4 + 8 * s) * 16) =
                make_float4(lg[s][0], lg[s][1], lg[s][2], lg[s][3]);
    }
    __syncthreads();

    if (tid < 128) {
        const float* msc = (const float*)(sm + T_MSC);
        int rg = tid >> 5, lr = tid & 31, h = tid & 15;
        float l0 = msc[0], l1 = msc[1], l2 = msc[2], l3 = msc[3];
#pragma unroll
        for (int cg = 0; cg < 4; ++cg) {
            float4 pp = *(const float4*)(sm + T_SHP + ((rg * 4 + cg) * 32 + lr) * 16);
            l0 += pp.x; l1 += pp.y; l2 += pp.z; l3 += pp.w;
        }
        float tt = fminf(fmaxf(msc[4 + h], 0.2f), 10.f);
        float it = 1.f / tt;
        float m = fmaxf(fmaxf(l0, l1), fmaxf(l2, l3));
        float e0 = expf((l0 - m) * it), e1 = expf((l1 - m) * it);
        float e2 = expf((l2 - m) * it), e3 = expf((l3 - m) * it);
        float inv = 1.f / (e0 + e1 + e2 + e3);
        float q0 = e0 * inv, q1 = e1 * inv, q2 = e2 * inv, q3 = e3 * inv;
        q0 = fmaxf(q0, fminf(fmaxf(msc[20 + h * 4 + 0], 1e-7f), 0.1f));
        q1 = fmaxf(q1, fminf(fmaxf(msc[20 + h * 4 + 1], 1e-7f), 0.1f));
        q2 = fmaxf(q2, fminf(fmaxf(msc[20 + h * 4 + 2], 1e-7f), 0.1f));
        q3 = fmaxf(q3, fminf(fmaxf(msc[20 + h * 4 + 3], 1e-7f), 0.1f));
        inv = 1.f / (q0 + q1 + q2 + q3);
        *(float4*)&out[(size_t)(tok0 * 16 + tid) * 4] =
            make_float4(q0 * inv, q1 * inv, q2 * inv, q3 * inv);
    }
}

extern "C" void kernel_launch(void* const* d_in, const int* in_sizes, int n_in,
                              void* d_out, int out_size) {
    const float* hidden = (const float*)d_in[0];
    const float* br0    = (const float*)d_in[1];
    const float* br1    = (const float*)d_in[2];
    const float* br2    = (const float*)d_in[3];
    const float* br3    = (const float*)d_in[4];
    const float* W1     = (const float*)d_in[5];
    const float* b1     = (const float*)d_in[6];
    const float* W2     = (const float*)d_in[7];
    const float* b2     = (const float*)d_in[8];
    const float* epsf   = (const float*)d_in[9];
    const float* temp   = (const float*)d_in[10];
    float* out = (float*)d_out;

    cudaFuncSetAttribute(k_hid,  cudaFuncAttributeMaxDynamicSharedMemorySize, H_SMEM);
    cudaFuncSetAttribute(k_tail, cudaFuncAttributeMaxDynamicSharedMemorySize, T_SMEM);

    k_prep<<<173, 128>>>(W1);
    k_hid<<<128, 256, H_SMEM>>>(hidden);
    k_tail<<<512, 512, T_SMEM>>>(br0, br1, br2, br3, b1, W2, b2, epsf, temp, out);
}

// round 9
// speedup vs baseline: 1.2291x; 1.0164x over previous
#include <cuda_runtime.h>
#include <cuda_bf16.h>
#include <math.h>

typedef unsigned int uint32;

// ============================================================================
// HeadGroupedFusionGate, mma.sync bf16 3-term split (x*w ~ xh*wh + xl*wh + xh*wl).
// R9: two kernels only.
//   k_pre  : blocks 0..127  = hidden GEMM (inline W1->bf16 conversion, reg-
//            prefetched A and B) -> g_hidc partials
//            blocks 128..172 = tail weight chunks 16..20 -> g_Wh/g_Wl + statw
//   k_tail : R8 tail (bulk-DMA B, pipelined A, 32x32 warp tiles) + epilogue
// ============================================================================

__device__ uint4 g_WhV[21 * 1088];    // [chunk][k=64][n=136 pad] bf16
__device__ uint4 g_WlV[21 * 1088];
__device__ float g_hidc[2][4096 * 128];

// ---- PTX helpers ----
__device__ __forceinline__ uint32 smem_u32(const void* p) {
    uint32 a;
    asm("{ .reg .u64 t; cvta.to.shared.u64 t, %1; cvt.u32.u64 %0, t; }" : "=r"(a) : "l"(p));
    return a;
}
__device__ __forceinline__ void ldsm4(uint32* r, uint32 a) {
    asm volatile("ldmatrix.sync.aligned.m8n8.x4.shared.b16 {%0,%1,%2,%3}, [%4];"
        : "=r"(r[0]), "=r"(r[1]), "=r"(r[2]), "=r"(r[3]) : "r"(a));
}
__device__ __forceinline__ void ldsm4t(uint32* r, uint32 a) {
    asm volatile("ldmatrix.sync.aligned.m8n8.x4.trans.shared.b16 {%0,%1,%2,%3}, [%4];"
        : "=r"(r[0]), "=r"(r[1]), "=r"(r[2]), "=r"(r[3]) : "r"(a));
}
__device__ __forceinline__ void mma16816(float* d, const uint32* a, uint32 b0, uint32 b1) {
    asm volatile("mma.sync.aligned.m16n8k16.row.col.f32.bf16.bf16.f32 "
        "{%0,%1,%2,%3}, {%4,%5,%6,%7}, {%8,%9}, {%0,%1,%2,%3};"
        : "+f"(d[0]), "+f"(d[1]), "+f"(d[2]), "+f"(d[3])
        : "r"(a[0]), "r"(a[1]), "r"(a[2]), "r"(a[3]), "r"(b0), "r"(b1));
}
__device__ __forceinline__ void cvtpair(float v0, float v1, uint32& h, uint32& l) {
    __nv_bfloat162 hp = __floats2bfloat162_rn(v0, v1);
    h = *(uint32*)&hp;
    float r0 = v0 - __bfloat162float(hp.x);
    float r1 = v1 - __bfloat162float(hp.y);
    __nv_bfloat162 lp = __floats2bfloat162_rn(r0, r1);
    l = *(uint32*)&lp;
}
#define MBAR_INIT(mb, n) \
    asm volatile("mbarrier.init.shared.b64 [%0], %1;" :: "r"(mb), "r"(n) : "memory")
#define MBAR_EXPECT(mb, tx) \
    asm volatile("mbarrier.arrive.expect_tx.shared.b64 _, [%0], %1;" :: "r"(mb), "r"(tx) : "memory")
__device__ __forceinline__ void bulk_cp(uint32 dst, const void* src, uint32 bytes, uint32 mb) {
    asm volatile("cp.async.bulk.shared::cta.global.mbarrier::complete_tx::bytes "
                 "[%0], [%1], %2, [%3];" :: "r"(dst), "l"(src), "r"(bytes), "r"(mb) : "memory");
}
__device__ __forceinline__ void mbar_wait(uint32 mb, uint32 parity) {
    asm volatile(
        "{\n\t.reg .pred P;\n\t"
        "W%=:\n\tmbarrier.try_wait.parity.acquire.cta.shared::cta.b64 P, [%0], %1, 0x989680;\n\t"
        "@P bra.uni D%=;\n\tbra.uni W%=;\n\tD%=:\n\t}"
        :: "r"(mb), "r"(parity) : "memory");
}

// warp tile 32 rows x 32 cols; NK k16 steps; A and B from smem via ldmatrix.
// B rows = 272 B, k16-stride = 4352 B.
template <int NK, int SA>
__device__ __forceinline__ void mma_chunk(float (&acc)[2][4][4],
                                          uint32 Ah, uint32 Al,
                                          uint32 Bh, uint32 Bl, int lane) {
    uint32 aoff = (uint32)((lane & 15) * SA + (lane >> 4) * 16);
    uint32 boff = (uint32)(((lane & 7) + ((lane >> 3) & 1) * 8) * 272 + ((lane >> 4) & 1) * 16);
#pragma unroll
    for (int k = 0; k < NK; ++k) {
        uint32 ah[2][4], al[2][4];
        ldsm4(ah[0], Ah + aoff + k * 32);
        ldsm4(ah[1], Ah + 16 * SA + aoff + k * 32);
        ldsm4(al[0], Al + aoff + k * 32);
        ldsm4(al[1], Al + 16 * SA + aoff + k * 32);
        uint32 bh0[4], bh1[4], bl0[4], bl1[4];
        uint32 bb = boff + k * 4352;
        ldsm4t(bh0, Bh + bb); ldsm4t(bh1, Bh + bb + 32);
        ldsm4t(bl0, Bl + bb); ldsm4t(bl1, Bl + bb + 32);
#pragma unroll
        for (int m = 0; m < 2; ++m) {
            mma16816(acc[m][0], ah[m], bh0[0], bh0[1]);
            mma16816(acc[m][1], ah[m], bh0[2], bh0[3]);
            mma16816(acc[m][2], ah[m], bh1[0], bh1[1]);
            mma16816(acc[m][3], ah[m], bh1[2], bh1[3]);
            mma16816(acc[m][0], al[m], bh0[0], bh0[1]);
            mma16816(acc[m][1], al[m], bh0[2], bh0[3]);
            mma16816(acc[m][2], al[m], bh1[0], bh1[1]);
            mma16816(acc[m][3], al[m], bh1[2], bh1[3]);
            mma16816(acc[m][0], ah[m], bl0[0], bl0[1]);
            mma16816(acc[m][1], ah[m], bl0[2], bl0[3]);
            mma16816(acc[m][2], ah[m], bl1[0], bl1[1]);
            mma16816(acc[m][3], ah[m], bl1[2], bl1[3]);
        }
    }
}

// ============================================================================
// k_pre: blocks 0..127 = hidden GEMM (bid>>1 = 64-token group, bid&1 = K half,
//        8 chunks of 64). 256 thr = 8 warps: rowg=w>>2 (2x32 rows), colg=w&3.
//        B converted inline from W1 (reg-prefetched). Single A/B smem buffers.
//        blocks 128..172 = tail weight prep (chunks 16..20 + statw + pad).
// smem (hid): AHI 0 (9216) | ALO 9216 | BH 18432 (17408) | BL 35840. = 53248.
// ============================================================================
#define P_ALO  9216
#define P_BH   18432
#define P_BL   35840
#define P_SMEM 53248

__global__ void __launch_bounds__(256) k_pre(const float* __restrict__ hidden,
                                             const float* __restrict__ W1) {
    int tid = threadIdx.x;
    if (blockIdx.x >= 128) {            // ---- tail-weight prep path ----
        int b2 = blockIdx.x - 128;      // 0..44
        __nv_bfloat16* Wh = (__nv_bfloat16*)g_WhV;
        __nv_bfloat16* Wl = (__nv_bfloat16*)g_WlV;
        if (tid >= 128) return;
        if (b2 < 32) {                  // chunks 16..19: rr 1024..1279, 8 rows/blk
            int rr0 = 1024 + b2 * 8;
#pragma unroll
            for (int j = 0; j < 8; ++j) {
                int rr = rr0 + j;
                int row = 1792 + (rr - 1024);
                float v = W1[(size_t)row * 128 + tid];
                __nv_bfloat16 h = __float2bfloat16_rn(v);
                Wh[rr * 136 + tid] = h;
                Wl[rr * 136 + tid] = __float2bfloat16_rn(v - __bfloat162float(h));
            }
        } else if (b2 < 44) {           // statw colsum k = b2-32
            int k = b2 - 32;
            int row0 = 1024 + (k / 3) * 192 + (k % 3) * 64;
            float s = 0.f;
#pragma unroll 8
            for (int d = 0; d < 64; ++d) s += W1[(size_t)(row0 + d) * 128 + tid];
            __nv_bfloat16 h = __float2bfloat16_rn(s);
            Wh[(1280 + k) * 136 + tid] = h;
            Wl[(1280 + k) * 136 + tid] = __float2bfloat16_rn(s - __bfloat162float(h));
        } else {                        // zero pad k 12..15 of chunk 20
            __nv_bfloat16 z = __float2bfloat16_rn(0.f);
#pragma unroll
            for (int k = 12; k < 16; ++k) {
                Wh[(1280 + k) * 136 + tid] = z;
                Wl[(1280 + k) * 136 + tid] = z;
            }
        }
        return;
    }

    // ---- hidden GEMM path ----
    extern __shared__ char sm[];
    uint32 sb = smem_u32(sm);
    int lane = tid & 31, w = tid >> 5;
    int rb = (w >> 2) * 32, cb = (w & 3) * 32;
    int tg = blockIdx.x >> 1, khalf = blockIdx.x & 1;
    int tok0 = tg * 64;
    const float4* hidf4 = (const float4*)hidden;
    const float4* W1f4  = (const float4*)W1;

    float acc[2][4][4];
#pragma unroll
    for (int m = 0; m < 2; ++m)
#pragma unroll
        for (int n = 0; n < 4; ++n)
#pragma unroll
            for (int i = 0; i < 4; ++i) acc[m][n][i] = 0.f;

    // prefetch chunk 0 (A: 1024 f4, B: 2048 f4)
    float4 fa[4], fw[8];
    {
        int c = khalf * 8;
#pragma unroll
        for (int i = 0; i < 4; ++i) {
            int u = tid + 256 * i;
            fa[i] = hidf4[(size_t)(tok0 + (u >> 4)) * 256 + c * 16 + (u & 15)];
        }
#pragma unroll
        for (int i = 0; i < 8; ++i) {
            int u = tid + 256 * i;
            fw[i] = W1f4[(size_t)(c * 64 + (u >> 5)) * 32 + (u & 31)];
        }
    }

    for (int p = 0; p < 8; ++p) {
        // STS A(p)
#pragma unroll
        for (int i = 0; i < 4; ++i) {
            int u = tid + 256 * i;
            int row = u >> 4, seg = u & 15;
            uint32 h0, l0, h1, l1;
            cvtpair(fa[i].x, fa[i].y, h0, l0);
            cvtpair(fa[i].z, fa[i].w, h1, l1);
            *(uint2*)(sm + row * 144 + seg * 8) = make_uint2(h0, h1);
            *(uint2*)(sm + P_ALO + row * 144 + seg * 8) = make_uint2(l0, l1);
        }
        // STS B(p)
#pragma unroll
        for (int i = 0; i < 8; ++i) {
            int u = tid + 256 * i;
            int row = u >> 5, seg = u & 31;
            uint32 h0, l0, h1, l1;
            cvtpair(fw[i].x, fw[i].y, h0, l0);
            cvtpair(fw[i].z, fw[i].w, h1, l1);
            *(uint2*)(sm + P_BH + row * 272 + seg * 8) = make_uint2(h0, h1);
            *(uint2*)(sm + P_BL + row * 272 + seg * 8) = make_uint2(l0, l1);
        }
        if (p < 7) {   // prefetch chunk p+1
            int c = khalf * 8 + p + 1;
#pragma unroll
            for (int i = 0; i < 4; ++i) {
                int u = tid + 256 * i;
                fa[i] = hidf4[(size_t)(tok0 + (u >> 4)) * 256 + c * 16 + (u & 15)];
            }
#pragma unroll
            for (int i = 0; i < 8; ++i) {
                int u = tid + 256 * i;
                fw[i] = W1f4[(size_t)(c * 64 + (u >> 5)) * 32 + (u & 31)];
            }
        }
        __syncthreads();
        uint32 bbase = sb + P_BH + cb * 2;
        mma_chunk<4, 144>(acc, sb + rb * 144, sb + P_ALO + rb * 144,
                          bbase, bbase + 17408, lane);
        __syncthreads();   // protect single A/B buffers before next STS
    }

    float* dst = g_hidc[khalf];
    int q4 = lane >> 2, q = lane & 3;
#pragma unroll
    for (int m = 0; m < 2; ++m)
#pragma unroll
        for (int nt = 0; nt < 4; ++nt) {
            int c0 = cb + nt * 8 + 2 * q;
            int rA = rb + 16 * m + q4;
            *(float2*)&dst[(size_t)(tok0 + rA) * 128 + c0] = make_float2(acc[m][nt][0], acc[m][nt][1]);
            *(float2*)&dst[(size_t)(tok0 + rA + 8) * 128 + c0] = make_float2(acc[m][nt][2], acc[m][nt][3]);
        }
}

// ============================================================================
// k_tail (R8): grid 512, 512 thr = 16 warps, CTA = 8 tokens x 16 heads.
// ============================================================================
#define T_BB   73728
#define T_ASH  143360
#define T_ASL  149504
#define T_HID  155648
#define T_W2S  159744
#define T_SHP  161792
#define T_MSC  169984
#define T_MB   170496
#define T_SMEM 170512

__global__ void __launch_bounds__(512, 1) k_tail(
    const float* __restrict__ br0, const float* __restrict__ br1,
    const float* __restrict__ br2, const float* __restrict__ br3,
    const float* __restrict__ b1, const float* __restrict__ W2,
    const float* __restrict__ b2, const float* __restrict__ epsf,
    const float* __restrict__ temp, float* __restrict__ out) {
    extern __shared__ char sm[];
    uint32 sb = smem_u32(sm);
    int tid = threadIdx.x, lane = tid & 31, w = tid >> 5;
    int rowg = w >> 2, colg = w & 3;
    int rb = rowg * 32, cb = colg * 32;
    int q4 = lane >> 2, q = lane & 3;
    int tok0 = blockIdx.x * 8;
    const float* brs[4] = {br0, br1, br2, br3};
    const char* WhB = (const char*)g_WhV;
    const char* WlB = (const char*)g_WlV;

    if (tid == 0) { MBAR_INIT(sb + T_MB, 1); MBAR_INIT(sb + T_MB + 8, 1); }
    if (tid < 256) {
        int row = tid >> 5, c4 = tid & 31;
        float4 a0 = *(const float4*)&g_hidc[0][(size_t)(tok0 + row) * 128 + c4 * 4];
        float4 a1 = *(const float4*)&g_hidc[1][(size_t)(tok0 + row) * 128 + c4 * 4];
        float4 c = ((const float4*)b1)[c4];
        *(float4*)(sm + T_HID + tid * 16) = make_float4(
            a0.x + a1.x + c.x, a0.y + a1.y + c.y, a0.z + a1.z + c.z, a0.w + a1.w + c.w);
    }
    if (tid < 128) {
        *(float4*)(sm + T_W2S + tid * 16) = ((const float4*)W2)[tid];
        *(uint2*)(sm + T_ASH + tid * 48 + 24) = make_uint2(0u, 0u);
        *(uint2*)(sm + T_ASL + tid * 48 + 24) = make_uint2(0u, 0u);
    }
    {
        float* msc = (float*)(sm + T_MSC);
        if (tid < 4)  msc[tid] = b2[tid];
        if (tid < 16) msc[4 + tid] = temp[tid];
        if (tid < 64) msc[20 + tid] = epsf[tid];
    }
    __syncthreads();

    float acc[2][4][4];
#pragma unroll
    for (int m = 0; m < 2; ++m)
#pragma unroll
        for (int n = 0; n < 4; ++n)
#pragma unroll
            for (int i = 0; i < 4; ++i) acc[m][n][i] = 0.f;

    uint32 ph0 = 0, ph1 = 0;
    if (tid == 0) {
        MBAR_EXPECT(sb + T_MB, 34816u);
        bulk_cp(sb + T_BB, WhB + (size_t)16 * 17408, 17408u, sb + T_MB);
        bulk_cp(sb + T_BB + 17408, WlB + (size_t)16 * 17408, 17408u, sb + T_MB);
    }
    float4 f[4];
    {
        const float4* src = (const float4*)brs[0] + (size_t)tok0 * 256;
#pragma unroll
        for (int i = 0; i < 4; ++i) f[i] = src[tid + 512 * i];
    }

    for (int p = 0; p < 5; ++p) {
        int ab = (p & 1) * 36864;
        if (p < 4) {
#pragma unroll
            for (int i = 0; i < 4; ++i) {
                float4 v = f[i];
                int row = (tid >> 4) + 32 * i, seg = tid & 15;
                float s = v.x + v.y + v.z + v.w;
                float s2 = fmaf(v.x, v.x, fmaf(v.y, v.y, fmaf(v.z, v.z, v.w * v.w)));
                float mx = fmaxf(fmaxf(v.x, v.y), fmaxf(v.z, v.w));
#pragma unroll
                for (int d = 1; d <= 8; d <<= 1) {
                    s += __shfl_xor_sync(0xffffffffu, s, d);
                    s2 += __shfl_xor_sync(0xffffffffu, s2, d);
                    mx = fmaxf(mx, __shfl_xor_sync(0xffffffffu, mx, d));
                }
                if (seg < 3) {
                    float sval = (seg == 0) ? s * 0.015625f
                               : (seg == 1) ? sqrtf(fmaxf(s2 * 0.015625f, 1e-8f)) : mx;
                    __nv_bfloat16 h = __float2bfloat16_rn(sval);
                    *(__nv_bfloat16*)(sm + T_ASH + row * 48 + (p * 3 + seg) * 2) = h;
                    *(__nv_bfloat16*)(sm + T_ASL + row * 48 + (p * 3 + seg) * 2) =
                        __float2bfloat16_rn(sval - __bfloat162float(h));
                }
                uint32 h0, l0, h1, l1;
                cvtpair(v.x, v.y, h0, l0);
                cvtpair(v.z, v.w, h1, l1);
                *(uint2*)(sm + ab + row * 144 + seg * 8) = make_uint2(h0, h1);
                *(uint2*)(sm + ab + 18432 + row * 144 + seg * 8) = make_uint2(l0, l1);
            }
            if (p < 3) {
                const float4* src = (const float4*)brs[p + 1] + (size_t)tok0 * 256;
#pragma unroll
                for (int i = 0; i < 4; ++i) f[i] = src[tid + 512 * i];
            }
        }
        __syncthreads();
        if (p < 4 && tid == 0) {
            int chunk = (p + 1 < 4) ? 16 + p + 1 : 20;
            uint32 bytes = (p + 1 < 4) ? 17408u : 4352u;
            uint32 bbuf = sb + T_BB + ((p + 1) & 1) * 34816;
            uint32 mb = sb + T_MB + ((p + 1) & 1) * 8;
            MBAR_EXPECT(mb, bytes * 2);
            bulk_cp(bbuf, WhB + (size_t)chunk * 17408, bytes, mb);
            bulk_cp(bbuf + 17408, WlB + (size_t)chunk * 17408, bytes, mb);
        }
        if ((p & 1) == 0) { mbar_wait(sb + T_MB, ph0); ph0 ^= 1; }
        else              { mbar_wait(sb + T_MB + 8, ph1); ph1 ^= 1; }
        uint32 bbase = sb + T_BB + (p & 1) * 34816 + cb * 2;
        if (p < 4)
            mma_chunk<4, 144>(acc, sb + ab + rb * 144, sb + ab + 18432 + rb * 144,
                              bbase, bbase + 17408, lane);
        else
            mma_chunk<1, 48>(acc, sb + T_ASH + rb * 48, sb + T_ASL + rb * 48,
                             bbase, bbase + 17408, lane);
    }

    // ---- epilogue ----
    float lg[4][4];
#pragma unroll
    for (int s = 0; s < 4; ++s)
#pragma unroll
        for (int j = 0; j < 4; ++j) lg[s][j] = 0.f;
#pragma unroll
    for (int m = 0; m < 2; ++m) {
        int tokc = rowg * 2 + m;
#pragma unroll
        for (int nt = 0; nt < 4; ++nt) {
            int c0 = cb + nt * 8 + 2 * q;
            float2 hv = *(const float2*)(sm + T_HID + (tokc * 128 + c0) * 4);
            float4 wa = *(const float4*)(sm + T_W2S + c0 * 16);
            float4 wb = *(const float4*)(sm + T_W2S + (c0 + 1) * 16);
            float v0 = acc[m][nt][0] + hv.x, v1 = acc[m][nt][1] + hv.y;
            float v2 = acc[m][nt][2] + hv.x, v3 = acc[m][nt][3] + hv.y;
            float g0 = v0 * normcdff(v0), g1 = v1 * normcdff(v1);
            float g2 = v2 * normcdff(v2), g3 = v3 * normcdff(v3);
            lg[2 * m][0] = fmaf(g0, wa.x, fmaf(g1, wb.x, lg[2 * m][0]));
            lg[2 * m][1] = fmaf(g0, wa.y, fmaf(g1, wb.y, lg[2 * m][1]));
            lg[2 * m][2] = fmaf(g0, wa.z, fmaf(g1, wb.z, lg[2 * m][2]));
            lg[2 * m][3] = fmaf(g0, wa.w, fmaf(g1, wb.w, lg[2 * m][3]));
            lg[2 * m + 1][0] = fmaf(g2, wa.x, fmaf(g3, wb.x, lg[2 * m + 1][0]));
            lg[2 * m + 1][1] = fmaf(g2, wa.y, fmaf(g3, wb.y, lg[2 * m + 1][1]));
            lg[2 * m + 1][2] = fmaf(g2, wa.z, fmaf(g3, wb.z, lg[2 * m + 1][2]));
            lg[2 * m + 1][3] = fmaf(g2, wa.w, fmaf(g3, wb.w, lg[2 * m + 1][3]));
        }
    }
#pragma unroll
    for (int d = 1; d <= 2; d <<= 1)
#pragma unroll
        for (int s = 0; s < 4; ++s)
#pragma unroll
            for (int j = 0; j < 4; ++j)
                lg[s][j] += __shfl_xor_sync(0xffffffffu, lg[s][j], d);
    if (q == 0) {
#pragma unroll
        for (int s = 0; s < 4; ++s)
            *(float4*)(sm + T_SHP + (w * 32 + q4 + 8 * s) * 16) =
                make_float4(lg[s][0], lg[s][1], lg[s][2], lg[s][3]);
    }
    __syncthreads();

    if (tid < 128) {
        const float* msc = (const float*)(sm + T_MSC);
        int rg = tid >> 5, lr = tid & 31, h = tid & 15;
        float l0 = msc[0], l1 = msc[1], l2 = msc[2], l3 = msc[3];
#pragma unroll
        for (int cg = 0; cg < 4; ++cg) {
            float4 pp = *(const float4*)(sm + T_SHP + ((rg * 4 + cg) * 32 + lr) * 16);
            l0 += pp.x; l1 += pp.y; l2 += pp.z; l3 += pp.w;
        }
        float tt = fminf(fmaxf(msc[4 + h], 0.2f), 10.f);
        float it = 1.f / tt;
        float m = fmaxf(fmaxf(l0, l1), fmaxf(l2, l3));
        float e0 = expf((l0 - m) * it), e1 = expf((l1 - m) * it);
        float e2 = expf((l2 - m) * it), e3 = expf((l3 - m) * it);
        float inv = 1.f / (e0 + e1 + e2 + e3);
        float q0 = e0 * inv, q1 = e1 * inv, q2 = e2 * inv, q3 = e3 * inv;
        q0 = fmaxf(q0, fminf(fmaxf(msc[20 + h * 4 + 0], 1e-7f), 0.1f));
        q1 = fmaxf(q1, fminf(fmaxf(msc[20 + h * 4 + 1], 1e-7f), 0.1f));
        q2 = fmaxf(q2, fminf(fmaxf(msc[20 + h * 4 + 2], 1e-7f), 0.1f));
        q3 = fmaxf(q3, fminf(fmaxf(msc[20 + h * 4 + 3], 1e-7f), 0.1f));
        inv = 1.f / (q0 + q1 + q2 + q3);
        *(float4*)&out[(size_t)(tok0 * 16 + tid) * 4] =
            make_float4(q0 * inv, q1 * inv, q2 * inv, q3 * inv);
    }
}

extern "C" void kernel_launch(void* const* d_in, const int* in_sizes, int n_in,
                              void* d_out, int out_size) {
    const float* hidden = (const float*)d_in[0];
    const float* br0    = (const float*)d_in[1];
    const float* br1    = (const float*)d_in[2];
    const float* br2    = (const float*)d_in[3];
    const float* br3    = (const float*)d_in[4];
    const float* W1     = (const float*)d_in[5];
    const float* b1     = (const float*)d_in[6];
    const float* W2     = (const float*)d_in[7];
    const float* b2     = (const float*)d_in[8];
    const float* epsf   = (const float*)d_in[9];
    const float* temp   = (const float*)d_in[10];
    float* out = (float*)d_out;

    cudaFuncSetAttribute(k_pre,  cudaFuncAttributeMaxDynamicSharedMemorySize, P_SMEM);
    cudaFuncSetAttribute(k_tail, cudaFuncAttributeMaxDynamicSharedMemorySize, T_SMEM);

    k_pre<<<173, 256, P_SMEM>>>(hidden, W1);
    k_tail<<<512, 512, T_SMEM>>>(br0, br1, br2, br3, b1, W2, b2, epsf, temp, out);
}

// round 10
// speedup vs baseline: 1.3091x; 1.0651x over previous
#include <cuda_runtime.h>
#include <cuda_bf16.h>
#include <math.h>

typedef unsigned int uint32;

// ============================================================================
// HeadGroupedFusionGate, mma.sync bf16 3-term split (x*w ~ xh*wh + xl*wh + xh*wl).
// R10: k_tail shrunk to 4-token CTAs (64 rows, 256 thr, 102.9 KB smem) ->
//      2 CTAs/SM to cover phase-barrier latency (R9 profile: occ 24.8%,
//      issue 41%, tensor 23.7% => latency-bound, not HMMA-bound).
//   k_pre  : hidden GEMM (inline W1 conversion) + tail-weight prep (R9).
// ============================================================================

__device__ uint4 g_WhV[21 * 1088];    // [chunk][k=64][n=136 pad] bf16
__device__ uint4 g_WlV[21 * 1088];
__device__ float g_hidc[2][4096 * 128];

// ---- PTX helpers ----
__device__ __forceinline__ uint32 smem_u32(const void* p) {
    uint32 a;
    asm("{ .reg .u64 t; cvta.to.shared.u64 t, %1; cvt.u32.u64 %0, t; }" : "=r"(a) : "l"(p));
    return a;
}
__device__ __forceinline__ void ldsm4(uint32* r, uint32 a) {
    asm volatile("ldmatrix.sync.aligned.m8n8.x4.shared.b16 {%0,%1,%2,%3}, [%4];"
        : "=r"(r[0]), "=r"(r[1]), "=r"(r[2]), "=r"(r[3]) : "r"(a));
}
__device__ __forceinline__ void ldsm4t(uint32* r, uint32 a) {
    asm volatile("ldmatrix.sync.aligned.m8n8.x4.trans.shared.b16 {%0,%1,%2,%3}, [%4];"
        : "=r"(r[0]), "=r"(r[1]), "=r"(r[2]), "=r"(r[3]) : "r"(a));
}
__device__ __forceinline__ void mma16816(float* d, const uint32* a, uint32 b0, uint32 b1) {
    asm volatile("mma.sync.aligned.m16n8k16.row.col.f32.bf16.bf16.f32 "
        "{%0,%1,%2,%3}, {%4,%5,%6,%7}, {%8,%9}, {%0,%1,%2,%3};"
        : "+f"(d[0]), "+f"(d[1]), "+f"(d[2]), "+f"(d[3])
        : "r"(a[0]), "r"(a[1]), "r"(a[2]), "r"(a[3]), "r"(b0), "r"(b1));
}
__device__ __forceinline__ void cvtpair(float v0, float v1, uint32& h, uint32& l) {
    __nv_bfloat162 hp = __floats2bfloat162_rn(v0, v1);
    h = *(uint32*)&hp;
    float r0 = v0 - __bfloat162float(hp.x);
    float r1 = v1 - __bfloat162float(hp.y);
    __nv_bfloat162 lp = __floats2bfloat162_rn(r0, r1);
    l = *(uint32*)&lp;
}
#define MBAR_INIT(mb, n) \
    asm volatile("mbarrier.init.shared.b64 [%0], %1;" :: "r"(mb), "r"(n) : "memory")
#define MBAR_EXPECT(mb, tx) \
    asm volatile("mbarrier.arrive.expect_tx.shared.b64 _, [%0], %1;" :: "r"(mb), "r"(tx) : "memory")
__device__ __forceinline__ void bulk_cp(uint32 dst, const void* src, uint32 bytes, uint32 mb) {
    asm volatile("cp.async.bulk.shared::cta.global.mbarrier::complete_tx::bytes "
                 "[%0], [%1], %2, [%3];" :: "r"(dst), "l"(src), "r"(bytes), "r"(mb) : "memory");
}
__device__ __forceinline__ void mbar_wait(uint32 mb, uint32 parity) {
    asm volatile(
        "{\n\t.reg .pred P;\n\t"
        "W%=:\n\tmbarrier.try_wait.parity.acquire.cta.shared::cta.b64 P, [%0], %1, 0x989680;\n\t"
        "@P bra.uni D%=;\n\tbra.uni W%=;\n\tD%=:\n\t}"
        :: "r"(mb), "r"(parity) : "memory");
}

// warp tile 32 rows x 32 cols; NK k16 steps; A and B from smem via ldmatrix.
// B rows = 272 B, k16-stride = 4352 B.
template <int NK, int SA>
__device__ __forceinline__ void mma_chunk(float (&acc)[2][4][4],
                                          uint32 Ah, uint32 Al,
                                          uint32 Bh, uint32 Bl, int lane) {
    uint32 aoff = (uint32)((lane & 15) * SA + (lane >> 4) * 16);
    uint32 boff = (uint32)(((lane & 7) + ((lane >> 3) & 1) * 8) * 272 + ((lane >> 4) & 1) * 16);
#pragma unroll
    for (int k = 0; k < NK; ++k) {
        uint32 ah[2][4], al[2][4];
        ldsm4(ah[0], Ah + aoff + k * 32);
        ldsm4(ah[1], Ah + 16 * SA + aoff + k * 32);
        ldsm4(al[0], Al + aoff + k * 32);
        ldsm4(al[1], Al + 16 * SA + aoff + k * 32);
        uint32 bh0[4], bh1[4], bl0[4], bl1[4];
        uint32 bb = boff + k * 4352;
        ldsm4t(bh0, Bh + bb); ldsm4t(bh1, Bh + bb + 32);
        ldsm4t(bl0, Bl + bb); ldsm4t(bl1, Bl + bb + 32);
#pragma unroll
        for (int m = 0; m < 2; ++m) {
            mma16816(acc[m][0], ah[m], bh0[0], bh0[1]);
            mma16816(acc[m][1], ah[m], bh0[2], bh0[3]);
            mma16816(acc[m][2], ah[m], bh1[0], bh1[1]);
            mma16816(acc[m][3], ah[m], bh1[2], bh1[3]);
            mma16816(acc[m][0], al[m], bh0[0], bh0[1]);
            mma16816(acc[m][1], al[m], bh0[2], bh0[3]);
            mma16816(acc[m][2], al[m], bh1[0], bh1[1]);
            mma16816(acc[m][3], al[m], bh1[2], bh1[3]);
            mma16816(acc[m][0], ah[m], bl0[0], bl0[1]);
            mma16816(acc[m][1], ah[m], bl0[2], bl0[3]);
            mma16816(acc[m][2], ah[m], bl1[0], bl1[1]);
            mma16816(acc[m][3], ah[m], bl1[2], bl1[3]);
        }
    }
}

// ============================================================================
// k_pre (R9): blocks 0..127 hidden GEMM, 128..172 tail-weight prep.
// smem (hid): AHI 0 (9216) | ALO 9216 | BH 18432 (17408) | BL 35840. = 53248.
// ============================================================================
#define P_ALO  9216
#define P_BH   18432
#define P_BL   35840
#define P_SMEM 53248

__global__ void __launch_bounds__(256) k_pre(const float* __restrict__ hidden,
                                             const float* __restrict__ W1) {
    int tid = threadIdx.x;
    if (blockIdx.x >= 128) {            // ---- tail-weight prep path ----
        int b2 = blockIdx.x - 128;      // 0..44
        __nv_bfloat16* Wh = (__nv_bfloat16*)g_WhV;
        __nv_bfloat16* Wl = (__nv_bfloat16*)g_WlV;
        if (tid >= 128) return;
        if (b2 < 32) {
            int rr0 = 1024 + b2 * 8;
#pragma unroll
            for (int j = 0; j < 8; ++j) {
                int rr = rr0 + j;
                int row = 1792 + (rr - 1024);
                float v = W1[(size_t)row * 128 + tid];
                __nv_bfloat16 h = __float2bfloat16_rn(v);
                Wh[rr * 136 + tid] = h;
                Wl[rr * 136 + tid] = __float2bfloat16_rn(v - __bfloat162float(h));
            }
        } else if (b2 < 44) {
            int k = b2 - 32;
            int row0 = 1024 + (k / 3) * 192 + (k % 3) * 64;
            float s = 0.f;
#pragma unroll 8
            for (int d = 0; d < 64; ++d) s += W1[(size_t)(row0 + d) * 128 + tid];
            __nv_bfloat16 h = __float2bfloat16_rn(s);
            Wh[(1280 + k) * 136 + tid] = h;
            Wl[(1280 + k) * 136 + tid] = __float2bfloat16_rn(s - __bfloat162float(h));
        } else {
            __nv_bfloat16 z = __float2bfloat16_rn(0.f);
#pragma unroll
            for (int k = 12; k < 16; ++k) {
                Wh[(1280 + k) * 136 + tid] = z;
                Wl[(1280 + k) * 136 + tid] = z;
            }
        }
        return;
    }

    // ---- hidden GEMM path ----
    extern __shared__ char sm[];
    uint32 sb = smem_u32(sm);
    int lane = tid & 31, w = tid >> 5;
    int rb = (w >> 2) * 32, cb = (w & 3) * 32;
    int tg = blockIdx.x >> 1, khalf = blockIdx.x & 1;
    int tok0 = tg * 64;
    const float4* hidf4 = (const float4*)hidden;
    const float4* W1f4  = (const float4*)W1;

    float acc[2][4][4];
#pragma unroll
    for (int m = 0; m < 2; ++m)
#pragma unroll
        for (int n = 0; n < 4; ++n)
#pragma unroll
            for (int i = 0; i < 4; ++i) acc[m][n][i] = 0.f;

    float4 fa[4], fw[8];
    {
        int c = khalf * 8;
#pragma unroll
        for (int i = 0; i < 4; ++i) {
            int u = tid + 256 * i;
            fa[i] = hidf4[(size_t)(tok0 + (u >> 4)) * 256 + c * 16 + (u & 15)];
        }
#pragma unroll
        for (int i = 0; i < 8; ++i) {
            int u = tid + 256 * i;
            fw[i] = W1f4[(size_t)(c * 64 + (u >> 5)) * 32 + (u & 31)];
        }
    }

    for (int p = 0; p < 8; ++p) {
#pragma unroll
        for (int i = 0; i < 4; ++i) {
            int u = tid + 256 * i;
            int row = u >> 4, seg = u & 15;
            uint32 h0, l0, h1, l1;
            cvtpair(fa[i].x, fa[i].y, h0, l0);
            cvtpair(fa[i].z, fa[i].w, h1, l1);
            *(uint2*)(sm + row * 144 + seg * 8) = make_uint2(h0, h1);
            *(uint2*)(sm + P_ALO + row * 144 + seg * 8) = make_uint2(l0, l1);
        }
#pragma unroll
        for (int i = 0; i < 8; ++i) {
            int u = tid + 256 * i;
            int row = u >> 5, seg = u & 31;
            uint32 h0, l0, h1, l1;
            cvtpair(fw[i].x, fw[i].y, h0, l0);
            cvtpair(fw[i].z, fw[i].w, h1, l1);
            *(uint2*)(sm + P_BH + row * 272 + seg * 8) = make_uint2(h0, h1);
            *(uint2*)(sm + P_BL + row * 272 + seg * 8) = make_uint2(l0, l1);
        }
        if (p < 7) {
            int c = khalf * 8 + p + 1;
#pragma unroll
            for (int i = 0; i < 4; ++i) {
                int u = tid + 256 * i;
                fa[i] = hidf4[(size_t)(tok0 + (u >> 4)) * 256 + c * 16 + (u & 15)];
            }
#pragma unroll
            for (int i = 0; i < 8; ++i) {
                int u = tid + 256 * i;
                fw[i] = W1f4[(size_t)(c * 64 + (u >> 5)) * 32 + (u & 31)];
            }
        }
        __syncthreads();
        uint32 bbase = sb + P_BH + cb * 2;
        mma_chunk<4, 144>(acc, sb + rb * 144, sb + P_ALO + rb * 144,
                          bbase, bbase + 17408, lane);
        __syncthreads();
    }

    float* dst = g_hidc[khalf];
    int q4 = lane >> 2, q = lane & 3;
#pragma unroll
    for (int m = 0; m < 2; ++m)
#pragma unroll
        for (int nt = 0; nt < 4; ++nt) {
            int c0 = cb + nt * 8 + 2 * q;
            int rA = rb + 16 * m + q4;
            *(float2*)&dst[(size_t)(tok0 + rA) * 128 + c0] = make_float2(acc[m][nt][0], acc[m][nt][1]);
            *(float2*)&dst[(size_t)(tok0 + rA + 8) * 128 + c0] = make_float2(acc[m][nt][2], acc[m][nt][3]);
        }
}

// ============================================================================
// k_tail: grid 1024, 256 thr = 8 warps. CTA = 4 tokens x 16 heads = 64 rows.
// warp: rowg=w>>2 (2x32 rows), colg=w&3 (4x32 cols). 2 CTAs/SM.
// smem: AHI 0 (9216) | ALO 9216 | B[2] @18432 (34816 each) -> 88064
//       ASH @88064 (3072) | ASL @91136 (3072) | HID @94208 (2048)
//       W2S @96256 (2048) | SHP @98304 (4096) | MSC @102400 (512)
//       MB @102912 (16). Total 102928.
// ============================================================================
#define T_BB   18432
#define T_ASH  88064
#define T_ASL  91136
#define T_HID  94208
#define T_W2S  96256
#define T_SHP  98304
#define T_MSC  102400
#define T_MB   102912
#define T_SMEM 102928

__global__ void __launch_bounds__(256, 2) k_tail(
    const float* __restrict__ br0, const float* __restrict__ br1,
    const float* __restrict__ br2, const float* __restrict__ br3,
    const float* __restrict__ b1, const float* __restrict__ W2,
    const float* __restrict__ b2, const float* __restrict__ epsf,
    const float* __restrict__ temp, float* __restrict__ out) {
    extern __shared__ char sm[];
    uint32 sb = smem_u32(sm);
    int tid = threadIdx.x, lane = tid & 31, w = tid >> 5;
    int rowg = w >> 2, colg = w & 3;
    int rb = rowg * 32, cb = colg * 32;
    int q4 = lane >> 2, q = lane & 3;
    int tok0 = blockIdx.x * 4;
    const float* brs[4] = {br0, br1, br2, br3};
    const char* WhB = (const char*)g_WhV;
    const char* WlB = (const char*)g_WlV;

    if (tid == 0) { MBAR_INIT(sb + T_MB, 1); MBAR_INIT(sb + T_MB + 8, 1); }
    // prologue staging
    if (tid < 128) {
        int row = tid >> 5, c4 = tid & 31;     // 4 tokens x 32 f4
        float4 a0 = *(const float4*)&g_hidc[0][(size_t)(tok0 + row) * 128 + c4 * 4];
        float4 a1 = *(const float4*)&g_hidc[1][(size_t)(tok0 + row) * 128 + c4 * 4];
        float4 c = ((const float4*)b1)[c4];
        *(float4*)(sm + T_HID + tid * 16) = make_float4(
            a0.x + a1.x + c.x, a0.y + a1.y + c.y, a0.z + a1.z + c.z, a0.w + a1.w + c.w);
        *(float4*)(sm + T_W2S + tid * 16) = ((const float4*)W2)[tid];
    }
    if (tid < 64) {
        *(uint2*)(sm + T_ASH + tid * 48 + 24) = make_uint2(0u, 0u);
        *(uint2*)(sm + T_ASL + tid * 48 + 24) = make_uint2(0u, 0u);
    }
    {
        float* msc = (float*)(sm + T_MSC);
        if (tid < 4)  msc[tid] = b2[tid];
        if (tid < 16) msc[4 + tid] = temp[tid];
        if (tid < 64) msc[20 + tid] = epsf[tid];
    }

    float acc[2][4][4];
#pragma unroll
    for (int m = 0; m < 2; ++m)
#pragma unroll
        for (int n = 0; n < 4; ++n)
#pragma unroll
            for (int i = 0; i < 4; ++i) acc[m][n][i] = 0.f;

    uint32 ph0 = 0, ph1 = 0;
    if (tid == 0) {     // bulk B chunk0 (branch 0 weights)
        MBAR_EXPECT(sb + T_MB, 34816u);
        bulk_cp(sb + T_BB, WhB + (size_t)16 * 17408, 17408u, sb + T_MB);
        bulk_cp(sb + T_BB + 17408, WlB + (size_t)16 * 17408, 17408u, sb + T_MB);
    }
    float4 f[4];
    {
        const float4* src = (const float4*)brs[0] + (size_t)tok0 * 256;
#pragma unroll
        for (int i = 0; i < 4; ++i) f[i] = src[tid + 256 * i];
    }

    for (int p = 0; p < 5; ++p) {
        if (p > 0) __syncthreads();            // mma(p-1) done: A + B buf free
        if (p < 4) {
            // stats + convert + STS A(p); rows 64, half-warp (16 lanes) per row
#pragma unroll
            for (int i = 0; i < 4; ++i) {
                float4 v = f[i];
                int row = (tid >> 4) + 16 * i, seg = tid & 15;
                float s = v.x + v.y + v.z + v.w;
                float s2 = fmaf(v.x, v.x, fmaf(v.y, v.y, fmaf(v.z, v.z, v.w * v.w)));
                float mx = fmaxf(fmaxf(v.x, v.y), fmaxf(v.z, v.w));
#pragma unroll
                for (int d = 1; d <= 8; d <<= 1) {
                    s += __shfl_xor_sync(0xffffffffu, s, d);
                    s2 += __shfl_xor_sync(0xffffffffu, s2, d);
                    mx = fmaxf(mx, __shfl_xor_sync(0xffffffffu, mx, d));
                }
                if (seg < 3) {
                    float sval = (seg == 0) ? s * 0.015625f
                               : (seg == 1) ? sqrtf(fmaxf(s2 * 0.015625f, 1e-8f)) : mx;
                    __nv_bfloat16 h = __float2bfloat16_rn(sval);
                    *(__nv_bfloat16*)(sm + T_ASH + row * 48 + (p * 3 + seg) * 2) = h;
                    *(__nv_bfloat16*)(sm + T_ASL + row * 48 + (p * 3 + seg) * 2) =
                        __float2bfloat16_rn(sval - __bfloat162float(h));
                }
                uint32 h0, l0, h1, l1;
                cvtpair(v.x, v.y, h0, l0);
                cvtpair(v.z, v.w, h1, l1);
                *(uint2*)(sm + row * 144 + seg * 8) = make_uint2(h0, h1);
                *(uint2*)(sm + 9216 + row * 144 + seg * 8) = make_uint2(l0, l1);
            }
            if (p < 3) {   // LDG A(p+1)
                const float4* src = (const float4*)brs[p + 1] + (size_t)tok0 * 256;
#pragma unroll
                for (int i = 0; i < 4; ++i) f[i] = src[tid + 256 * i];
            }
        }
        __syncthreads();
        if (p < 4 && tid == 0) {   // bulk B(p+1)
            int chunk = (p + 1 < 4) ? 16 + p + 1 : 20;
            uint32 bytes = (p + 1 < 4) ? 17408u : 4352u;
            uint32 bbuf = sb + T_BB + ((p + 1) & 1) * 34816;
            uint32 mb = sb + T_MB + ((p + 1) & 1) * 8;
            MBAR_EXPECT(mb, bytes * 2);
            bulk_cp(bbuf, WhB + (size_t)chunk * 17408, bytes, mb);
            bulk_cp(bbuf + 17408, WlB + (size_t)chunk * 17408, bytes, mb);
        }
        if ((p & 1) == 0) { mbar_wait(sb + T_MB, ph0); ph0 ^= 1; }
        else              { mbar_wait(sb + T_MB + 8, ph1); ph1 ^= 1; }
        uint32 bbase = sb + T_BB + (p & 1) * 34816 + cb * 2;
        if (p < 4)
            mma_chunk<4, 144>(acc, sb + rb * 144, sb + 9216 + rb * 144,
                              bbase, bbase + 17408, lane);
        else
            mma_chunk<1, 48>(acc, sb + T_ASH + rb * 48, sb + T_ASL + rb * 48,
                             bbase, bbase + 17408, lane);
    }

    // ---- epilogue: gelu + W2 partial logits ----
    float lg[4][4];
#pragma unroll
    for (int s = 0; s < 4; ++s)
#pragma unroll
        for (int j = 0; j < 4; ++j) lg[s][j] = 0.f;
#pragma unroll
    for (int m = 0; m < 2; ++m) {
        int tokc = rowg * 2 + m;
#pragma unroll
        for (int nt = 0; nt < 4; ++nt) {
            int c0 = cb + nt * 8 + 2 * q;
            float2 hv = *(const float2*)(sm + T_HID + (tokc * 128 + c0) * 4);
            float4 wa = *(const float4*)(sm + T_W2S + c0 * 16);
            float4 wb = *(const float4*)(sm + T_W2S + (c0 + 1) * 16);
            float v0 = acc[m][nt][0] + hv.x, v1 = acc[m][nt][1] + hv.y;
            float v2 = acc[m][nt][2] + hv.x, v3 = acc[m][nt][3] + hv.y;
            float g0 = v0 * normcdff(v0), g1 = v1 * normcdff(v1);
            float g2 = v2 * normcdff(v2), g3 = v3 * normcdff(v3);
            lg[2 * m][0] = fmaf(g0, wa.x, fmaf(g1, wb.x, lg[2 * m][0]));
            lg[2 * m][1] = fmaf(g0, wa.y, fmaf(g1, wb.y, lg[2 * m][1]));
            lg[2 * m][2] = fmaf(g0, wa.z, fmaf(g1, wb.z, lg[2 * m][2]));
            lg[2 * m][3] = fmaf(g0, wa.w, fmaf(g1, wb.w, lg[2 * m][3]));
            lg[2 * m + 1][0] = fmaf(g2, wa.x, fmaf(g3, wb.x, lg[2 * m + 1][0]));
            lg[2 * m + 1][1] = fmaf(g2, wa.y, fmaf(g3, wb.y, lg[2 * m + 1][1]));
            lg[2 * m + 1][2] = fmaf(g2, wa.z, fmaf(g3, wb.z, lg[2 * m + 1][2]));
            lg[2 * m + 1][3] = fmaf(g2, wa.w, fmaf(g3, wb.w, lg[2 * m + 1][3]));
        }
    }
#pragma unroll
    for (int d = 1; d <= 2; d <<= 1)
#pragma unroll
        for (int s = 0; s < 4; ++s)
#pragma unroll
            for (int j = 0; j < 4; ++j)
                lg[s][j] += __shfl_xor_sync(0xffffffffu, lg[s][j], d);
    if (q == 0) {
#pragma unroll
        for (int s = 0; s < 4; ++s)
            *(float4*)(sm + T_SHP + (colg * 64 + rb + q4 + 8 * s) * 16) =
                make_float4(lg[s][0], lg[s][1], lg[s][2], lg[s][3]);
    }
    __syncthreads();

    if (tid < 64) {
        const float* msc = (const float*)(sm + T_MSC);
        int h = tid & 15;
        float l0 = msc[0], l1 = msc[1], l2 = msc[2], l3 = msc[3];
#pragma unroll
        for (int cg = 0; cg < 4; ++cg) {
            float4 pp = *(const float4*)(sm + T_SHP + (cg * 64 + tid) * 16);
            l0 += pp.x; l1 += pp.y; l2 += pp.z; l3 += pp.w;
        }
        float tt = fminf(fmaxf(msc[4 + h], 0.2f), 10.f);
        float it = 1.f / tt;
        float m = fmaxf(fmaxf(l0, l1), fmaxf(l2, l3));
        float e0 = expf((l0 - m) * it), e1 = expf((l1 - m) * it);
        float e2 = expf((l2 - m) * it), e3 = expf((l3 - m) * it);
        float inv = 1.f / (e0 + e1 + e2 + e3);
        float q0 = e0 * inv, q1 = e1 * inv, q2 = e2 * inv, q3 = e3 * inv;
        q0 = fmaxf(q0, fminf(fmaxf(msc[20 + h * 4 + 0], 1e-7f), 0.1f));
        q1 = fmaxf(q1, fminf(fmaxf(msc[20 + h * 4 + 1], 1e-7f), 0.1f));
        q2 = fmaxf(q2, fminf(fmaxf(msc[20 + h * 4 + 2], 1e-7f), 0.1f));
        q3 = fmaxf(q3, fminf(fmaxf(msc[20 + h * 4 + 3], 1e-7f), 0.1f));
        inv = 1.f / (q0 + q1 + q2 + q3);
        *(float4*)&out[(size_t)(tok0 * 16 + tid) * 4] =
            make_float4(q0 * inv, q1 * inv, q2 * inv, q3 * inv);
    }
}

extern "C" void kernel_launch(void* const* d_in, const int* in_sizes, int n_in,
                              void* d_out, int out_size) {
    const float* hidden = (const float*)d_in[0];
    const float* br0    = (const float*)d_in[1];
    const float* br1    = (const float*)d_in[2];
    const float* br2    = (const float*)d_in[3];
    const float* br3    = (const float*)d_in[4];
    const float* W1     = (const float*)d_in[5];
    const float* b1     = (const float*)d_in[6];
    const float* W2     = (const float*)d_in[7];
    const float* b2     = (const float*)d_in[8];
    const float* epsf   = (const float*)d_in[9];
    const float* temp   = (const float*)d_in[10];
    float* out = (float*)d_out;

    cudaFuncSetAttribute(k_pre,  cudaFuncAttributeMaxDynamicSharedMemorySize, P_SMEM);
    cudaFuncSetAttribute(k_tail, cudaFuncAttributeMaxDynamicSharedMemorySize, T_SMEM);

    k_pre<<<173, 256, P_SMEM>>>(hidden, W1);
    k_tail<<<1024, 256, T_SMEM>>>(br0, br1, br2, br3, b1, W2, b2, epsf, temp, out);
}

// round 11
// speedup vs baseline: 1.4225x; 1.0866x over previous
#include <cuda_runtime.h>
#include <cuda_bf16.h>
#include <math.h>

typedef unsigned int uint32;

// ============================================================================
// HeadGroupedFusionGate, mma.sync bf16 3-term split (x*w ~ xh*wh + xl*wh + xh*wl).
// R11: break the register occupancy cap. k_tail: __launch_bounds__(256,3),
//      single-buffer A+B (68.1 KB smem), low-reg mma (one B half live),
//      no persistent A prefetch -> 3 CTAs/SM (24 warps).
// ============================================================================

__device__ uint4 g_WhV[21 * 1088];    // [chunk][k=64][n=136 pad] bf16
__device__ uint4 g_WlV[21 * 1088];
__device__ float g_hidc[2][4096 * 128];

// ---- PTX helpers ----
__device__ __forceinline__ uint32 smem_u32(const void* p) {
    uint32 a;
    asm("{ .reg .u64 t; cvta.to.shared.u64 t, %1; cvt.u32.u64 %0, t; }" : "=r"(a) : "l"(p));
    return a;
}
__device__ __forceinline__ void ldsm4(uint32* r, uint32 a) {
    asm volatile("ldmatrix.sync.aligned.m8n8.x4.shared.b16 {%0,%1,%2,%3}, [%4];"
        : "=r"(r[0]), "=r"(r[1]), "=r"(r[2]), "=r"(r[3]) : "r"(a));
}
__device__ __forceinline__ void ldsm4t(uint32* r, uint32 a) {
    asm volatile("ldmatrix.sync.aligned.m8n8.x4.trans.shared.b16 {%0,%1,%2,%3}, [%4];"
        : "=r"(r[0]), "=r"(r[1]), "=r"(r[2]), "=r"(r[3]) : "r"(a));
}
__device__ __forceinline__ void mma16816(float* d, const uint32* a, uint32 b0, uint32 b1) {
    asm volatile("mma.sync.aligned.m16n8k16.row.col.f32.bf16.bf16.f32 "
        "{%0,%1,%2,%3}, {%4,%5,%6,%7}, {%8,%9}, {%0,%1,%2,%3};"
        : "+f"(d[0]), "+f"(d[1]), "+f"(d[2]), "+f"(d[3])
        : "r"(a[0]), "r"(a[1]), "r"(a[2]), "r"(a[3]), "r"(b0), "r"(b1));
}
__device__ __forceinline__ void cvtpair(float v0, float v1, uint32& h, uint32& l) {
    __nv_bfloat162 hp = __floats2bfloat162_rn(v0, v1);
    h = *(uint32*)&hp;
    float r0 = v0 - __bfloat162float(hp.x);
    float r1 = v1 - __bfloat162float(hp.y);
    __nv_bfloat162 lp = __floats2bfloat162_rn(r0, r1);
    l = *(uint32*)&lp;
}
#define MBAR_INIT(mb, n) \
    asm volatile("mbarrier.init.shared.b64 [%0], %1;" :: "r"(mb), "r"(n) : "memory")
#define MBAR_EXPECT(mb, tx) \
    asm volatile("mbarrier.arrive.expect_tx.shared.b64 _, [%0], %1;" :: "r"(mb), "r"(tx) : "memory")
__device__ __forceinline__ void bulk_cp(uint32 dst, const void* src, uint32 bytes, uint32 mb) {
    asm volatile("cp.async.bulk.shared::cta.global.mbarrier::complete_tx::bytes "
                 "[%0], [%1], %2, [%3];" :: "r"(dst), "l"(src), "r"(bytes), "r"(mb) : "memory");
}
__device__ __forceinline__ void mbar_wait(uint32 mb, uint32 parity) {
    asm volatile(
        "{\n\t.reg .pred P;\n\t"
        "W%=:\n\tmbarrier.try_wait.parity.acquire.cta.shared::cta.b64 P, [%0], %1, 0x989680;\n\t"
        "@P bra.uni D%=;\n\tbra.uni W%=;\n\tD%=:\n\t}"
        :: "r"(mb), "r"(parity) : "memory");
}

// warp tile 32 rows x 32 cols; NK k16 steps; low-register version: only one
// 16-col B half (8 frag regs) live at a time. B rows 272 B, k16-stride 4352 B.
template <int NK, int SA>
__device__ __forceinline__ void mma_chunk(float (&acc)[2][4][4],
                                          uint32 Ah, uint32 Al,
                                          uint32 Bh, uint32 Bl, int lane) {
    uint32 aoff = (uint32)((lane & 15) * SA + (lane >> 4) * 16);
    uint32 boff = (uint32)(((lane & 7) + ((lane >> 3) & 1) * 8) * 272 + ((lane >> 4) & 1) * 16);
#pragma unroll
    for (int k = 0; k < NK; ++k) {
        uint32 ah[2][4], al[2][4];
        ldsm4(ah[0], Ah + aoff + k * 32);
        ldsm4(ah[1], Ah + 16 * SA + aoff + k * 32);
        ldsm4(al[0], Al + aoff + k * 32);
        ldsm4(al[1], Al + 16 * SA + aoff + k * 32);
        uint32 bb = boff + k * 4352;
#pragma unroll
        for (int half = 0; half < 2; ++half) {
            uint32 bh[4], bl[4];
            ldsm4t(bh, Bh + bb + half * 32);
            ldsm4t(bl, Bl + bb + half * 32);
#pragma unroll
            for (int m = 0; m < 2; ++m) {
                mma16816(acc[m][2 * half + 0], ah[m], bh[0], bh[1]);
                mma16816(acc[m][2 * half + 1], ah[m], bh[2], bh[3]);
                mma16816(acc[m][2 * half + 0], al[m], bh[0], bh[1]);
                mma16816(acc[m][2 * half + 1], al[m], bh[2], bh[3]);
                mma16816(acc[m][2 * half + 0], ah[m], bl[0], bl[1]);
                mma16816(acc[m][2 * half + 1], ah[m], bl[2], bl[3]);
            }
        }
    }
}

// ============================================================================
// k_pre (R9): blocks 0..127 hidden GEMM, 128..172 tail-weight prep.
// smem (hid): AHI 0 (9216) | ALO 9216 | BH 18432 (17408) | BL 35840. = 53248.
// ============================================================================
#define P_ALO  9216
#define P_BH   18432
#define P_BL   35840
#define P_SMEM 53248

__global__ void __launch_bounds__(256) k_pre(const float* __restrict__ hidden,
                                             const float* __restrict__ W1) {
    int tid = threadIdx.x;
    if (blockIdx.x >= 128) {            // ---- tail-weight prep path ----
        int b2 = blockIdx.x - 128;      // 0..44
        __nv_bfloat16* Wh = (__nv_bfloat16*)g_WhV;
        __nv_bfloat16* Wl = (__nv_bfloat16*)g_WlV;
        if (tid >= 128) return;
        if (b2 < 32) {
            int rr0 = 1024 + b2 * 8;
#pragma unroll
            for (int j = 0; j < 8; ++j) {
                int rr = rr0 + j;
                int row = 1792 + (rr - 1024);
                float v = W1[(size_t)row * 128 + tid];
                __nv_bfloat16 h = __float2bfloat16_rn(v);
                Wh[rr * 136 + tid] = h;
                Wl[rr * 136 + tid] = __float2bfloat16_rn(v - __bfloat162float(h));
            }
        } else if (b2 < 44) {
            int k = b2 - 32;
            int row0 = 1024 + (k / 3) * 192 + (k % 3) * 64;
            float s = 0.f;
#pragma unroll 8
            for (int d = 0; d < 64; ++d) s += W1[(size_t)(row0 + d) * 128 + tid];
            __nv_bfloat16 h = __float2bfloat16_rn(s);
            Wh[(1280 + k) * 136 + tid] = h;
            Wl[(1280 + k) * 136 + tid] = __float2bfloat16_rn(s - __bfloat162float(h));
        } else {
            __nv_bfloat16 z = __float2bfloat16_rn(0.f);
#pragma unroll
            for (int k = 12; k < 16; ++k) {
                Wh[(1280 + k) * 136 + tid] = z;
                Wl[(1280 + k) * 136 + tid] = z;
            }
        }
        return;
    }

    // ---- hidden GEMM path ----
    extern __shared__ char sm[];
    uint32 sb = smem_u32(sm);
    int lane = tid & 31, w = tid >> 5;
    int rb = (w >> 2) * 32, cb = (w & 3) * 32;
    int tg = blockIdx.x >> 1, khalf = blockIdx.x & 1;
    int tok0 = tg * 64;
    const float4* hidf4 = (const float4*)hidden;
    const float4* W1f4  = (const float4*)W1;

    float acc[2][4][4];
#pragma unroll
    for (int m = 0; m < 2; ++m)
#pragma unroll
        for (int n = 0; n < 4; ++n)
#pragma unroll
            for (int i = 0; i < 4; ++i) acc[m][n][i] = 0.f;

    float4 fa[4], fw[8];
    {
        int c = khalf * 8;
#pragma unroll
        for (int i = 0; i < 4; ++i) {
            int u = tid + 256 * i;
            fa[i] = hidf4[(size_t)(tok0 + (u >> 4)) * 256 + c * 16 + (u & 15)];
        }
#pragma unroll
        for (int i = 0; i < 8; ++i) {
            int u = tid + 256 * i;
            fw[i] = W1f4[(size_t)(c * 64 + (u >> 5)) * 32 + (u & 31)];
        }
    }

    for (int p = 0; p < 8; ++p) {
#pragma unroll
        for (int i = 0; i < 4; ++i) {
            int u = tid + 256 * i;
            int row = u >> 4, seg = u & 15;
            uint32 h0, l0, h1, l1;
            cvtpair(fa[i].x, fa[i].y, h0, l0);
            cvtpair(fa[i].z, fa[i].w, h1, l1);
            *(uint2*)(sm + row * 144 + seg * 8) = make_uint2(h0, h1);
            *(uint2*)(sm + P_ALO + row * 144 + seg * 8) = make_uint2(l0, l1);
        }
#pragma unroll
        for (int i = 0; i < 8; ++i) {
            int u = tid + 256 * i;
            int row = u >> 5, seg = u & 31;
            uint32 h0, l0, h1, l1;
            cvtpair(fw[i].x, fw[i].y, h0, l0);
            cvtpair(fw[i].z, fw[i].w, h1, l1);
            *(uint2*)(sm + P_BH + row * 272 + seg * 8) = make_uint2(h0, h1);
            *(uint2*)(sm + P_BL + row * 272 + seg * 8) = make_uint2(l0, l1);
        }
        if (p < 7) {
            int c = khalf * 8 + p + 1;
#pragma unroll
            for (int i = 0; i < 4; ++i) {
                int u = tid + 256 * i;
                fa[i] = hidf4[(size_t)(tok0 + (u >> 4)) * 256 + c * 16 + (u & 15)];
            }
#pragma unroll
            for (int i = 0; i < 8; ++i) {
                int u = tid + 256 * i;
                fw[i] = W1f4[(size_t)(c * 64 + (u >> 5)) * 32 + (u & 31)];
            }
        }
        __syncthreads();
        uint32 bbase = sb + P_BH + cb * 2;
        mma_chunk<4, 144>(acc, sb + rb * 144, sb + P_ALO + rb * 144,
                          bbase, bbase + 17408, lane);
        __syncthreads();
    }

    float* dst = g_hidc[khalf];
    int q4 = lane >> 2, q = lane & 3;
#pragma unroll
    for (int m = 0; m < 2; ++m)
#pragma unroll
        for (int nt = 0; nt < 4; ++nt) {
            int c0 = cb + nt * 8 + 2 * q;
            int rA = rb + 16 * m + q4;
            *(float2*)&dst[(size_t)(tok0 + rA) * 128 + c0] = make_float2(acc[m][nt][0], acc[m][nt][1]);
            *(float2*)&dst[(size_t)(tok0 + rA + 8) * 128 + c0] = make_float2(acc[m][nt][2], acc[m][nt][3]);
        }
}

// ============================================================================
// k_tail: grid 1024, 256 thr = 8 warps. CTA = 4 tokens x 16 heads = 64 rows.
// __launch_bounds__(256,3): <=84 regs -> 3 CTAs/SM (24 warps).
// Single A buffer, single B buffer, single mbar.
// smem: AHI 0 (9216) | ALO 9216 | B 18432 (34816: hi+lo) |
//       ASH 53248 (3072) | ASL 56320 (3072) | HID 59392 (2048)
//       W2S 61440 (2048) | SHP 63488 (4096) | MSC 67584 (512) | MB 68096 (8)
//       Total 68104 -> pad 68112.
// ============================================================================
#define T_BB   18432
#define T_ASH  53248
#define T_ASL  56320
#define T_HID  59392
#define T_W2S  61440
#define T_SHP  63488
#define T_MSC  67584
#define T_MB   68096
#define T_SMEM 68112

__global__ void __launch_bounds__(256, 3) k_tail(
    const float* __restrict__ br0, const float* __restrict__ br1,
    const float* __restrict__ br2, const float* __restrict__ br3,
    const float* __restrict__ b1, const float* __restrict__ W2,
    const float* __restrict__ b2, const float* __restrict__ epsf,
    const float* __restrict__ temp, float* __restrict__ out) {
    extern __shared__ char sm[];
    uint32 sb = smem_u32(sm);
    int tid = threadIdx.x, lane = tid & 31, w = tid >> 5;
    int rowg = w >> 2, colg = w & 3;
    int rb = rowg * 32, cb = colg * 32;
    int q4 = lane >> 2, q = lane & 3;
    int tok0 = blockIdx.x * 4;
    const float* brs[4] = {br0, br1, br2, br3};
    const char* WhB = (const char*)g_WhV;
    const char* WlB = (const char*)g_WlV;

    if (tid == 0) {
        MBAR_INIT(sb + T_MB, 1);
        // bulk B chunk0 (branch 0 weights) as early as possible
        MBAR_EXPECT(sb + T_MB, 34816u);
        bulk_cp(sb + T_BB, WhB + (size_t)16 * 17408, 17408u, sb + T_MB);
        bulk_cp(sb + T_BB + 17408, WlB + (size_t)16 * 17408, 17408u, sb + T_MB);
    }
    // prologue staging
    if (tid < 128) {
        int row = tid >> 5, c4 = tid & 31;     // 4 tokens x 32 f4
        float4 a0 = *(const float4*)&g_hidc[0][(size_t)(tok0 + row) * 128 + c4 * 4];
        float4 a1 = *(const float4*)&g_hidc[1][(size_t)(tok0 + row) * 128 + c4 * 4];
        float4 c = ((const float4*)b1)[c4];
        *(float4*)(sm + T_HID + tid * 16) = make_float4(
            a0.x + a1.x + c.x, a0.y + a1.y + c.y, a0.z + a1.z + c.z, a0.w + a1.w + c.w);
        *(float4*)(sm + T_W2S + tid * 16) = ((const float4*)W2)[tid];
    }
    if (tid < 64) {
        *(uint2*)(sm + T_ASH + tid * 48 + 24) = make_uint2(0u, 0u);
        *(uint2*)(sm + T_ASL + tid * 48 + 24) = make_uint2(0u, 0u);
    }
    {
        float* msc = (float*)(sm + T_MSC);
        if (tid < 4)  msc[tid] = b2[tid];
        if (tid < 16) msc[4 + tid] = temp[tid];
        if (tid < 64) msc[20 + tid] = epsf[tid];
    }

    float acc[2][4][4];
#pragma unroll
    for (int m = 0; m < 2; ++m)
#pragma unroll
        for (int n = 0; n < 4; ++n)
#pragma unroll
            for (int i = 0; i < 4; ++i) acc[m][n][i] = 0.f;

    uint32 ph = 0;
    for (int p = 0; p < 5; ++p) {
        if (p > 0) {
            __syncthreads();                   // mma(p-1) done: A + B free
            if (tid == 0) {                    // issue bulk B(p) immediately
                int chunk = (p < 4) ? 16 + p : 20;
                uint32 bytes = (p < 4) ? 17408u : 4352u;
                MBAR_EXPECT(sb + T_MB, bytes * 2);
                bulk_cp(sb + T_BB, WhB + (size_t)chunk * 17408, bytes, sb + T_MB);
                bulk_cp(sb + T_BB + 17408, WlB + (size_t)chunk * 17408, bytes, sb + T_MB);
            }
        }
        if (p < 4) {
            // LDG A(p) fresh (no persistent prefetch regs), stats, convert, STS
#pragma unroll
            for (int i = 0; i < 4; ++i) {
                float4 v = ((const float4*)brs[p])[(size_t)tok0 * 256 + tid + 256 * i];
                int row = (tid >> 4) + 16 * i, seg = tid & 15;
                float s = v.x + v.y + v.z + v.w;
                float s2 = fmaf(v.x, v.x, fmaf(v.y, v.y, fmaf(v.z, v.z, v.w * v.w)));
                float mx = fmaxf(fmaxf(v.x, v.y), fmaxf(v.z, v.w));
#pragma unroll
                for (int d = 1; d <= 8; d <<= 1) {
                    s += __shfl_xor_sync(0xffffffffu, s, d);
                    s2 += __shfl_xor_sync(0xffffffffu, s2, d);
                    mx = fmaxf(mx, __shfl_xor_sync(0xffffffffu, mx, d));
                }
                if (seg < 3) {
                    float sval = (seg == 0) ? s * 0.015625f
                               : (seg == 1) ? sqrtf(fmaxf(s2 * 0.015625f, 1e-8f)) : mx;
                    __nv_bfloat16 h = __float2bfloat16_rn(sval);
                    *(__nv_bfloat16*)(sm + T_ASH + row * 48 + (p * 3 + seg) * 2) = h;
                    *(__nv_bfloat16*)(sm + T_ASL + row * 48 + (p * 3 + seg) * 2) =
                        __float2bfloat16_rn(sval - __bfloat162float(h));
                }
                uint32 h0, l0, h1, l1;
                cvtpair(v.x, v.y, h0, l0);
                cvtpair(v.z, v.w, h1, l1);
                *(uint2*)(sm + row * 144 + seg * 8) = make_uint2(h0, h1);
                *(uint2*)(sm + 9216 + row * 144 + seg * 8) = make_uint2(l0, l1);
            }
        }
        __syncthreads();                       // A(p) visible
        mbar_wait(sb + T_MB, ph); ph ^= 1;     // B(p) arrived
        uint32 bbase = sb + T_BB + cb * 2;
        if (p < 4)
            mma_chunk<4, 144>(acc, sb + rb * 144, sb + 9216 + rb * 144,
                              bbase, bbase + 17408, lane);
        else
            mma_chunk<1, 48>(acc, sb + T_ASH + rb * 48, sb + T_ASL + rb * 48,
                             bbase, bbase + 17408, lane);
    }

    // ---- epilogue: gelu + W2 partial logits ----
    float lg[4][4];
#pragma unroll
    for (int s = 0; s < 4; ++s)
#pragma unroll
        for (int j = 0; j < 4; ++j) lg[s][j] = 0.f;
#pragma unroll
    for (int m = 0; m < 2; ++m) {
        int tokc = rowg * 2 + m;
#pragma unroll
        for (int nt = 0; nt < 4; ++nt) {
            int c0 = cb + nt * 8 + 2 * q;
            float2 hv = *(const float2*)(sm + T_HID + (tokc * 128 + c0) * 4);
            float4 wa = *(const float4*)(sm + T_W2S + c0 * 16);
            float4 wb = *(const float4*)(sm + T_W2S + (c0 + 1) * 16);
            float v0 = acc[m][nt][0] + hv.x, v1 = acc[m][nt][1] + hv.y;
            float v2 = acc[m][nt][2] + hv.x, v3 = acc[m][nt][3] + hv.y;
            float g0 = v0 * normcdff(v0), g1 = v1 * normcdff(v1);
            float g2 = v2 * normcdff(v2), g3 = v3 * normcdff(v3);
            lg[2 * m][0] = fmaf(g0, wa.x, fmaf(g1, wb.x, lg[2 * m][0]));
            lg[2 * m][1] = fmaf(g0, wa.y, fmaf(g1, wb.y, lg[2 * m][1]));
            lg[2 * m][2] = fmaf(g0, wa.z, fmaf(g1, wb.z, lg[2 * m][2]));
            lg[2 * m][3] = fmaf(g0, wa.w, fmaf(g1, wb.w, lg[2 * m][3]));
            lg[2 * m + 1][0] = fmaf(g2, wa.x, fmaf(g3, wb.x, lg[2 * m + 1][0]));
            lg[2 * m + 1][1] = fmaf(g2, wa.y, fmaf(g3, wb.y, lg[2 * m + 1][1]));
            lg[2 * m + 1][2] = fmaf(g2, wa.z, fmaf(g3, wb.z, lg[2 * m + 1][2]));
            lg[2 * m + 1][3] = fmaf(g2, wa.w, fmaf(g3, wb.w, lg[2 * m + 1][3]));
        }
    }
#pragma unroll
    for (int d = 1; d <= 2; d <<= 1)
#pragma unroll
        for (int s = 0; s < 4; ++s)
#pragma unroll
            for (int j = 0; j < 4; ++j)
                lg[s][j] += __shfl_xor_sync(0xffffffffu, lg[s][j], d);
    if (q == 0) {
#pragma unroll
        for (int s = 0; s < 4; ++s)
            *(float4*)(sm + T_SHP + (colg * 64 + rb + q4 + 8 * s) * 16) =
                make_float4(lg[s][0], lg[s][1], lg[s][2], lg[s][3]);
    }
    __syncthreads();

    if (tid < 64) {
        const float* msc = (const float*)(sm + T_MSC);
        int h = tid & 15;
        float l0 = msc[0], l1 = msc[1], l2 = msc[2], l3 = msc[3];
#pragma unroll
        for (int cg = 0; cg < 4; ++cg) {
            float4 pp = *(const float4*)(sm + T_SHP + (cg * 64 + tid) * 16);
            l0 += pp.x; l1 += pp.y; l2 += pp.z; l3 += pp.w;
        }
        float tt = fminf(fmaxf(msc[4 + h], 0.2f), 10.f);
        float it = 1.f / tt;
        float m = fmaxf(fmaxf(l0, l1), fmaxf(l2, l3));
        float e0 = expf((l0 - m) * it), e1 = expf((l1 - m) * it);
        float e2 = expf((l2 - m) * it), e3 = expf((l3 - m) * it);
        float inv = 1.f / (e0 + e1 + e2 + e3);
        float q0 = e0 * inv, q1 = e1 * inv, q2 = e2 * inv, q3 = e3 * inv;
        q0 = fmaxf(q0, fminf(fmaxf(msc[20 + h * 4 + 0], 1e-7f), 0.1f));
        q1 = fmaxf(q1, fminf(fmaxf(msc[20 + h * 4 + 1], 1e-7f), 0.1f));
        q2 = fmaxf(q2, fminf(fmaxf(msc[20 + h * 4 + 2], 1e-7f), 0.1f));
        q3 = fmaxf(q3, fminf(fmaxf(msc[20 + h * 4 + 3], 1e-7f), 0.1f));
        inv = 1.f / (q0 + q1 + q2 + q3);
        *(float4*)&out[(size_t)(tok0 * 16 + tid) * 4] =
            make_float4(q0 * inv, q1 * inv, q2 * inv, q3 * inv);
    }
}

extern "C" void kernel_launch(void* const* d_in, const int* in_sizes, int n_in,
                              void* d_out, int out_size) {
    const float* hidden = (const float*)d_in[0];
    const float* br0    = (const float*)d_in[1];
    const float* br1    = (const float*)d_in[2];
    const float* br2    = (const float*)d_in[3];
    const float* br3    = (const float*)d_in[4];
    const float* W1     = (const float*)d_in[5];
    const float* b1     = (const float*)d_in[6];
    const float* W2     = (const float*)d_in[7];
    const float* b2     = (const float*)d_in[8];
    const float* epsf   = (const float*)d_in[9];
    const float* temp   = (const float*)d_in[10];
    float* out = (float*)d_out;

    cudaFuncSetAttribute(k_pre,  cudaFuncAttributeMaxDynamicSharedMemorySize, P_SMEM);
    cudaFuncSetAttribute(k_tail, cudaFuncAttributeMaxDynamicSharedMemorySize, T_SMEM);

    k_pre<<<173, 256, P_SMEM>>>(hidden, W1);
    k_tail<<<1024, 256, T_SMEM>>>(br0, br1, br2, br3, b1, W2, b2, epsf, temp, out);
}